// round 12
// baseline (speedup 1.0000x reference)
#include <cuda_runtime.h>
#include <cuda_bf16.h>
#include <cstdint>

// ---------------------------------------------------------------------------
// Hetero-RGCN, 2 layers, output = chemical nodes.
// GEMM: mma.sync bf16 (HMMA) 3-term split, cp.async double-buffer + ldmatrix.
// Aggregation: CSR, unroll-4 register accumulation (MLP>=4), modes:
//   WRITE / ACC / ACC_FINAL (fused leaky-relu + bf16 hi/lo split).
// R12 = R11 resubmitted (R11 bench was an infra failure, not a kernel result):
//   fused GEMM||AGG launches (block-role split); MLP-4 agg fixes the R9
//   occupancy trap; 5 of 6 aggs hidden behind GEMMs.
// ---------------------------------------------------------------------------

#define NNODE 50000
#define DIM   256
#define NE    400000
#define SCAN_N (4 * NNODE)                   // 200000
#define SCAN_BLKS ((SCAN_N + 1023) / 1024)   // 196

#define GEMM_BLOCKS 782                      // 2 col x 391 row (128x128 tiles)
#define AGG_BLOCKS  12500                    // 50000 nodes * 64 thr / 256

#define AGG_WRITE 0
#define AGG_ACC   1
#define AGG_FINAL 2

__device__ __align__(16) float g_Wh0[NNODE * DIM];
__device__ __align__(16) float g_Wh1[NNODE * DIM];
__device__ __align__(16) float g_agg_ch[NNODE * DIM];
__device__ __align__(16) float g_agg_ge[NNODE * DIM];
__device__ __align__(16) int   g_cnt[SCAN_N];
__device__ __align__(16) int   g_off[SCAN_N + 1];
__device__ __align__(16) int   g_cur[SCAN_N];
__device__ __align__(16) int   g_bsum[SCAN_BLKS + 1];
__device__ __align__(16) int   g_ebuf[4 * NE];
__device__ __align__(16) __nv_bfloat16 g_Wt[6 * 2 * 65536];
__device__ __align__(16) __nv_bfloat16 g_Abf[4 * 2 * NNODE * DIM];

// ============================ small utility kernels =========================
__global__ void zero_2i(int* __restrict__ a, int* __restrict__ b, int n) {
    int i = blockIdx.x * blockDim.x + threadIdx.x;
    if (i < n) { a[i] = 0; b[i] = 0; }
}

__global__ void count_deg4(const int* __restrict__ d0, const int* __restrict__ d1,
                           const int* __restrict__ d2, const int* __restrict__ d3,
                           int* __restrict__ cnt) {
    int i = blockIdx.x * blockDim.x + threadIdx.x;
    if (i >= 4 * NE) return;
    int t = i / NE, e = i - t * NE;
    const int* d = (t == 0) ? d0 : (t == 1) ? d1 : (t == 2) ? d2 : d3;
    atomicAdd(&cnt[t * NNODE + d[e]], 1);
}

// ---- fast 3-pass exclusive scan over cnt[SCAN_N] -> off[SCAN_N+1] ----
__global__ __launch_bounds__(256)
void scan_p1(const int* __restrict__ cnt, int* __restrict__ off,
             int* __restrict__ bsum) {
    __shared__ int swarp[8];
    const int tid = threadIdx.x;
    const int lane = tid & 31, wrp = tid >> 5;
    const int i0 = blockIdx.x * 1024 + tid * 4;

    int v0 = 0, v1 = 0, v2 = 0, v3 = 0;
    if (i0 + 3 < SCAN_N) {
        int4 v = *reinterpret_cast<const int4*>(cnt + i0);
        v0 = v.x; v1 = v.y; v2 = v.z; v3 = v.w;
    } else {
        if (i0 + 0 < SCAN_N) v0 = cnt[i0 + 0];
        if (i0 + 1 < SCAN_N) v1 = cnt[i0 + 1];
        if (i0 + 2 < SCAN_N) v2 = cnt[i0 + 2];
        if (i0 + 3 < SCAN_N) v3 = cnt[i0 + 3];
    }
    int e1 = v0, e2 = v0 + v1, e3 = v0 + v1 + v2;
    int tsum = e3 + v3;

    int incl = tsum;
#pragma unroll
    for (int d = 1; d < 32; d <<= 1) {
        int u = __shfl_up_sync(0xffffffffu, incl, d);
        if (lane >= d) incl += u;
    }
    if (lane == 31) swarp[wrp] = incl;
    __syncthreads();
    if (wrp == 0 && lane < 8) {
        int w = swarp[lane];
        int wi = w;
#pragma unroll
        for (int d = 1; d < 8; d <<= 1) {
            int u = __shfl_up_sync(0xffu, wi, d);
            if (lane >= d) wi += u;
        }
        swarp[lane] = wi - w;
    }
    __syncthreads();
    int base = swarp[wrp] + (incl - tsum);

    if (i0 + 0 < SCAN_N) off[i0 + 0] = base;
    if (i0 + 1 < SCAN_N) off[i0 + 1] = base + e1;
    if (i0 + 2 < SCAN_N) off[i0 + 2] = base + e2;
    if (i0 + 3 < SCAN_N) off[i0 + 3] = base + e3;
    if (tid == 255) bsum[blockIdx.x] = base + tsum;
}

__global__ __launch_bounds__(256)
void scan_p2(int* __restrict__ bsum) {
    __shared__ int swarp[8];
    const int tid = threadIdx.x;
    const int lane = tid & 31, wrp = tid >> 5;
    int v = (tid < SCAN_BLKS) ? bsum[tid] : 0;
    int incl = v;
#pragma unroll
    for (int d = 1; d < 32; d <<= 1) {
        int u = __shfl_up_sync(0xffffffffu, incl, d);
        if (lane >= d) incl += u;
    }
    if (lane == 31) swarp[wrp] = incl;
    __syncthreads();
    if (wrp == 0 && lane < 8) {
        int w = swarp[lane];
        int wi = w;
#pragma unroll
        for (int d = 1; d < 8; d <<= 1) {
            int u = __shfl_up_sync(0xffu, wi, d);
            if (lane >= d) wi += u;
        }
        swarp[lane] = wi - w;
    }
    __syncthreads();
    if (tid < SCAN_BLKS) bsum[tid] = swarp[wrp] + (incl - v);
}

__global__ void scan_p3(int* __restrict__ off, const int* __restrict__ bsum) {
    int i = blockIdx.x * blockDim.x + threadIdx.x;
    if (i < SCAN_N) off[i] += bsum[i >> 10];
    if (i == 0) off[SCAN_N] = 4 * NE;
}

__global__ void scatter4(const int* __restrict__ s0, const int* __restrict__ d0,
                         const int* __restrict__ s1, const int* __restrict__ d1,
                         const int* __restrict__ s2, const int* __restrict__ d2,
                         const int* __restrict__ s3, const int* __restrict__ d3,
                         const int* __restrict__ off, int* __restrict__ cur,
                         int* __restrict__ ebuf) {
    int i = blockIdx.x * blockDim.x + threadIdx.x;
    if (i >= 4 * NE) return;
    int t = i / NE, e = i - t * NE;
    const int* s = (t == 0) ? s0 : (t == 1) ? s1 : (t == 2) ? s2 : s3;
    const int* d = (t == 0) ? d0 : (t == 1) ? d1 : (t == 2) ? d2 : d3;
    int dd = t * NNODE + d[e];
    int p = atomicAdd(&cur[dd], 1);
    ebuf[off[dd] + p] = s[e];
}

// Transpose + bf16 hi/lo split of one 256x256 weight: out[n][k] = W[k][n]
__global__ void split_w(const float* __restrict__ W,
                        __nv_bfloat16* __restrict__ hi,
                        __nv_bfloat16* __restrict__ lo) {
    int i = blockIdx.x * 256 + threadIdx.x;
    int n = i >> 8, k = i & 255;
    float w = W[k * 256 + n];
    __nv_bfloat16 h = __float2bfloat16_rn(w);
    hi[i] = h;
    lo[i] = __float2bfloat16_rn(w - __bfloat162float(h));
}

// fp32 activations -> bf16 hi/lo (embeddings; no lrelu)
__global__ void split_act(const float* __restrict__ x,
                          __nv_bfloat16* __restrict__ hi,
                          __nv_bfloat16* __restrict__ lo, int n4) {
    int i = blockIdx.x * blockDim.x + threadIdx.x;
    if (i >= n4) return;
    float4 v = reinterpret_cast<const float4*>(x)[i];
    __nv_bfloat162 h01, h23, l01, l23;
    h01.x = __float2bfloat16_rn(v.x);
    h01.y = __float2bfloat16_rn(v.y);
    h23.x = __float2bfloat16_rn(v.z);
    h23.y = __float2bfloat16_rn(v.w);
    l01.x = __float2bfloat16_rn(v.x - __bfloat162float(h01.x));
    l01.y = __float2bfloat16_rn(v.y - __bfloat162float(h01.y));
    l23.x = __float2bfloat16_rn(v.z - __bfloat162float(h23.x));
    l23.y = __float2bfloat16_rn(v.w - __bfloat162float(h23.y));
    uint2 hv, lv;
    hv.x = *reinterpret_cast<uint32_t*>(&h01);
    hv.y = *reinterpret_cast<uint32_t*>(&h23);
    lv.x = *reinterpret_cast<uint32_t*>(&l01);
    lv.y = *reinterpret_cast<uint32_t*>(&l23);
    *reinterpret_cast<uint2*>(hi + (size_t)i * 4) = hv;
    *reinterpret_cast<uint2*>(lo + (size_t)i * 4) = lv;
}

// ====================== GEMM body (device function) =========================
#define AST 40
#define STG_A_HI 0
#define STG_A_LO 10240
#define STG_B_HI 20480
#define STG_B_LO 30720
#define STG_BYTES 40960
#define SMEM_BYTES (2 * STG_BYTES)   // 81920

__device__ __forceinline__ uint32_t smem_u32(const void* p) {
    uint32_t a;
    asm("{ .reg .u64 t; cvta.to.shared.u64 t, %1; cvt.u32.u64 %0, t; }"
        : "=r"(a) : "l"(p));
    return a;
}

__device__ __forceinline__ void cp16(uint32_t s, const void* g, int sz) {
    asm volatile("cp.async.cg.shared.global [%0], [%1], 16, %2;"
                 :: "r"(s), "l"(g), "r"(sz));
}

__device__ __forceinline__ void ldm_x4(uint32_t* r, uint32_t addr) {
    asm volatile("ldmatrix.sync.aligned.m8n8.x4.shared.b16 {%0,%1,%2,%3}, [%4];"
                 : "=r"(r[0]), "=r"(r[1]), "=r"(r[2]), "=r"(r[3]) : "r"(addr));
}

__device__ __forceinline__ void mma_bf16(float* c, const uint32_t* a,
                                         const uint32_t* b) {
    asm volatile(
        "mma.sync.aligned.m16n8k16.row.col.f32.bf16.bf16.f32 "
        "{%0,%1,%2,%3}, {%4,%5,%6,%7}, {%8,%9}, {%0,%1,%2,%3};"
        : "+f"(c[0]), "+f"(c[1]), "+f"(c[2]), "+f"(c[3])
        : "r"(a[0]), "r"(a[1]), "r"(a[2]), "r"(a[3]), "r"(b[0]), "r"(b[1]));
}

__device__ void gemm_body(int bid,
                          const __nv_bfloat16* __restrict__ Ahi,
                          const __nv_bfloat16* __restrict__ Alo,
                          const __nv_bfloat16* __restrict__ Bhi,
                          const __nv_bfloat16* __restrict__ Blo,
                          const float* __restrict__ bias,
                          float* __restrict__ C, int M)
{
    extern __shared__ char smc[];
    const uint32_t smb = smem_u32(smc);

    const int tid = threadIdx.x;
    const int wid = tid >> 5;
    const int lid = tid & 31;
    const int wr = wid & 1;
    const int wc = wid >> 1;
    const int g = lid >> 2;
    const int t = lid & 3;
    const int row0 = (bid >> 1) * 128;
    const int col0 = (bid & 1) * 128;

    const int a_row_l = wr * 64 + (lid & 7) + ((lid >> 3) & 1) * 8;
    const int a_col_l = ((lid >> 4) & 1) * 8;
    const int b_row_l = wc * 32 + (lid & 7) + ((lid >> 4) & 1) * 8;
    const int b_col_l = ((lid >> 3) & 1) * 8;

    float acc[4][4][4];
#pragma unroll
    for (int i = 0; i < 4; i++)
#pragma unroll
        for (int j = 0; j < 4; j++)
#pragma unroll
            for (int k = 0; k < 4; k++) acc[i][j][k] = 0.f;

#define ISSUE_STAGE(stage, k0)                                                 \
    do {                                                                       \
        uint32_t sb = smb + (stage) * STG_BYTES;                               \
        _Pragma("unroll")                                                      \
        for (int it = 0; it < 2; ++it) {                                       \
            int i = it * 256 + tid;                                            \
            int r = i >> 2, ch = i & 3;                                        \
            uint32_t so = (uint32_t)(r * 80 + ch * 16);                        \
            int gr = row0 + r;                                                 \
            int sz = (gr < M) ? 16 : 0;                                        \
            size_t aoff = (size_t)(gr < M ? gr : 0) * 256 + (k0) + ch * 8;     \
            cp16(sb + STG_A_HI + so, Ahi + aoff, sz);                          \
            cp16(sb + STG_A_LO + so, Alo + aoff, sz);                          \
            size_t boff = (size_t)(col0 + r) * 256 + (k0) + ch * 8;            \
            cp16(sb + STG_B_HI + so, Bhi + boff, 16);                          \
            cp16(sb + STG_B_LO + so, Blo + boff, 16);                          \
        }                                                                      \
        asm volatile("cp.async.commit_group;" ::: "memory");                   \
    } while (0)

    ISSUE_STAGE(0, 0);

    for (int kb = 0; kb < 8; ++kb) {
        const int st = kb & 1;
        if (kb < 7) {
            ISSUE_STAGE(st ^ 1, (kb + 1) * 32);
            asm volatile("cp.async.wait_group 1;" ::: "memory");
        } else {
            asm volatile("cp.async.wait_group 0;" ::: "memory");
        }
        __syncthreads();

        const uint32_t stg = smb + st * STG_BYTES;

#pragma unroll
        for (int ks = 0; ks < 2; ++ks) {
            const int kk = ks * 16;
            uint32_t af[4][4], bh[2][4], bl[2][4];

#pragma unroll
            for (int np = 0; np < 2; ++np) {
                uint32_t boff = (uint32_t)((b_row_l + np * 16) * AST + kk + b_col_l) * 2;
                ldm_x4(bh[np], stg + STG_B_HI + boff);
                ldm_x4(bl[np], stg + STG_B_LO + boff);
            }
#pragma unroll
            for (int mt = 0; mt < 4; ++mt) {
                uint32_t aoff = (uint32_t)((a_row_l + mt * 16) * AST + kk + a_col_l) * 2;
                ldm_x4(af[mt], stg + STG_A_HI + aoff);
            }
#pragma unroll
            for (int mt = 0; mt < 4; ++mt)
#pragma unroll
                for (int nt = 0; nt < 4; ++nt)
                    mma_bf16(acc[mt][nt], af[mt], &bh[nt >> 1][(nt & 1) * 2]);
#pragma unroll
            for (int mt = 0; mt < 4; ++mt)
#pragma unroll
                for (int nt = 0; nt < 4; ++nt)
                    mma_bf16(acc[mt][nt], af[mt], &bl[nt >> 1][(nt & 1) * 2]);
#pragma unroll
            for (int mt = 0; mt < 4; ++mt) {
                uint32_t aoff = (uint32_t)((a_row_l + mt * 16) * AST + kk + a_col_l) * 2;
                ldm_x4(af[mt], stg + STG_A_LO + aoff);
            }
#pragma unroll
            for (int mt = 0; mt < 4; ++mt)
#pragma unroll
                for (int nt = 0; nt < 4; ++nt)
                    mma_bf16(acc[mt][nt], af[mt], &bh[nt >> 1][(nt & 1) * 2]);
        }
        __syncthreads();
    }

#pragma unroll
    for (int nt = 0; nt < 4; ++nt) {
        const int gc = col0 + wc * 32 + nt * 8 + t * 2;
        float2 bb = *reinterpret_cast<const float2*>(bias + gc);
#pragma unroll
        for (int mt = 0; mt < 4; ++mt) {
            int r0 = row0 + wr * 64 + mt * 16 + g;
            if (r0 < M) {
                float2 o;
                o.x = acc[mt][nt][0] + bb.x;
                o.y = acc[mt][nt][1] + bb.y;
                *reinterpret_cast<float2*>(C + (size_t)r0 * 256 + gc) = o;
            }
            if (r0 + 8 < M) {
                float2 o;
                o.x = acc[mt][nt][2] + bb.x;
                o.y = acc[mt][nt][3] + bb.y;
                *reinterpret_cast<float2*>(C + (size_t)(r0 + 8) * 256 + gc) = o;
            }
        }
    }
}

// ================== CSR aggregation body (unroll-4, MLP>=4) =================
__device__ void agg_body(int bid, const int* __restrict__ off,
                         const int* __restrict__ ebuf,
                         const float* __restrict__ Wh,
                         float* __restrict__ agg,
                         __nv_bfloat16* __restrict__ hi,
                         __nv_bfloat16* __restrict__ lo, int mode)
{
    int idx = bid * 256 + threadIdx.x;
    int node = idx >> 6;
    if (node >= NNODE) return;
    int q = (idx & 63) << 2;
    int e0 = __ldg(off + node), e1 = __ldg(off + node + 1);

    float4 s = make_float4(0.f, 0.f, 0.f, 0.f);
    int e = e0;
    for (; e + 4 <= e1; e += 4) {
        int i0 = __ldg(ebuf + e + 0);
        int i1 = __ldg(ebuf + e + 1);
        int i2 = __ldg(ebuf + e + 2);
        int i3 = __ldg(ebuf + e + 3);
        float4 v0 = *reinterpret_cast<const float4*>(Wh + (size_t)i0 * DIM + q);
        float4 v1 = *reinterpret_cast<const float4*>(Wh + (size_t)i1 * DIM + q);
        float4 v2 = *reinterpret_cast<const float4*>(Wh + (size_t)i2 * DIM + q);
        float4 v3 = *reinterpret_cast<const float4*>(Wh + (size_t)i3 * DIM + q);
        s.x += (v0.x + v1.x) + (v2.x + v3.x);
        s.y += (v0.y + v1.y) + (v2.y + v3.y);
        s.z += (v0.z + v1.z) + (v2.z + v3.z);
        s.w += (v0.w + v1.w) + (v2.w + v3.w);
    }
    for (; e < e1; ++e) {
        int si = __ldg(ebuf + e);
        float4 v = *reinterpret_cast<const float4*>(Wh + (size_t)si * DIM + q);
        s.x += v.x; s.y += v.y; s.z += v.z; s.w += v.w;
    }
    float w = (e1 > e0) ? 1.0f / (float)(e1 - e0) : 0.f;
    s.x *= w; s.y *= w; s.z *= w; s.w *= w;

    if (mode == AGG_WRITE) {
        *reinterpret_cast<float4*>(agg + (size_t)node * DIM + q) = s;
    } else if (mode == AGG_ACC) {
        if (e0 == e1) return;
        float4* out = reinterpret_cast<float4*>(agg + (size_t)node * DIM + q);
        float4 a = *out;
        a.x += s.x; a.y += s.y; a.z += s.z; a.w += s.w;
        *out = a;
    } else {  // AGG_FINAL: prev + s, leaky-relu, bf16 hi/lo split
        float4 a = *reinterpret_cast<const float4*>(agg + (size_t)node * DIM + q);
        a.x += s.x; a.y += s.y; a.z += s.z; a.w += s.w;
        a.x = a.x > 0.f ? a.x : 0.01f * a.x;
        a.y = a.y > 0.f ? a.y : 0.01f * a.y;
        a.z = a.z > 0.f ? a.z : 0.01f * a.z;
        a.w = a.w > 0.f ? a.w : 0.01f * a.w;
        __nv_bfloat162 h01, h23, l01, l23;
        h01.x = __float2bfloat16_rn(a.x);
        h01.y = __float2bfloat16_rn(a.y);
        h23.x = __float2bfloat16_rn(a.z);
        h23.y = __float2bfloat16_rn(a.w);
        l01.x = __float2bfloat16_rn(a.x - __bfloat162float(h01.x));
        l01.y = __float2bfloat16_rn(a.y - __bfloat162float(h01.y));
        l23.x = __float2bfloat16_rn(a.z - __bfloat162float(h23.x));
        l23.y = __float2bfloat16_rn(a.w - __bfloat162float(h23.y));
        uint2 hv, lv;
        hv.x = *reinterpret_cast<uint32_t*>(&h01);
        hv.y = *reinterpret_cast<uint32_t*>(&h23);
        lv.x = *reinterpret_cast<uint32_t*>(&l01);
        lv.y = *reinterpret_cast<uint32_t*>(&l23);
        *reinterpret_cast<uint2*>(hi + (size_t)node * DIM + q) = hv;
        *reinterpret_cast<uint2*>(lo + (size_t)node * DIM + q) = lv;
    }
}

// fused launch: blocks [0, nG) = GEMM, [nG, nG+AGG_BLOCKS) = aggregation
__global__ __launch_bounds__(256, 2)
void fused_gemm_agg(const __nv_bfloat16* __restrict__ Ahi,
                    const __nv_bfloat16* __restrict__ Alo,
                    const __nv_bfloat16* __restrict__ Bhi,
                    const __nv_bfloat16* __restrict__ Blo,
                    const float* __restrict__ bias,
                    float* __restrict__ C, int M,
                    const int* __restrict__ off, const int* __restrict__ ebuf,
                    const float* __restrict__ Whp, float* __restrict__ agg,
                    __nv_bfloat16* __restrict__ hi, __nv_bfloat16* __restrict__ lo,
                    int mode, int nG)
{
    if ((int)blockIdx.x < nG)
        gemm_body(blockIdx.x, Ahi, Alo, Bhi, Blo, bias, C, M);
    else
        agg_body(blockIdx.x - nG, off, ebuf, Whp, agg, hi, lo, mode);
}

// standalone aggregation (no smem -> full occupancy) for pipeline tails
__global__ void csr_agg(const int* __restrict__ off, const int* __restrict__ ebuf,
                        const float* __restrict__ Wh, float* __restrict__ agg,
                        __nv_bfloat16* __restrict__ hi,
                        __nv_bfloat16* __restrict__ lo, int mode)
{
    agg_body(blockIdx.x, off, ebuf, Wh, agg, hi, lo, mode);
}

// --------------------------------------------------------------------- host
extern "C" void kernel_launch(void* const* d_in, const int* in_sizes, int n_in,
                              void* d_out, int out_size)
{
    (void)n_in; (void)out_size;

    const float* emb[2] = {(const float*)d_in[0], (const float*)d_in[1]};
    const float *W1[4], *b1[4], *W2[4], *b2[4];
    const int *src[4], *dst[4];

    bool dict_order = (in_sizes[6] == NE);
    if (dict_order) {
        for (int t = 0; t < 4; t++) {
            const int base = 2 + 6 * t;
            W1[t]  = (const float*)d_in[base + 0];
            b1[t]  = (const float*)d_in[base + 1];
            W2[t]  = (const float*)d_in[base + 2];
            b2[t]  = (const float*)d_in[base + 3];
            src[t] = (const int*)  d_in[base + 4];
            dst[t] = (const int*)  d_in[base + 5];
        }
    } else {
        for (int t = 0; t < 4; t++) {
            W1[t]  = (const float*)d_in[2  + 2 * t];
            b1[t]  = (const float*)d_in[3  + 2 * t];
            W2[t]  = (const float*)d_in[10 + 2 * t];
            b2[t]  = (const float*)d_in[11 + 2 * t];
            src[t] = (const int*)  d_in[18 + 2 * t];
            dst[t] = (const int*)  d_in[19 + 2 * t];
        }
    }

    float *wh0, *wh1, *agg_ch, *agg_ge;
    int *cnt, *off, *cur, *bsum, *ebuf;
    __nv_bfloat16 *wt, *abf;
    cudaGetSymbolAddress((void**)&wh0,    g_Wh0);
    cudaGetSymbolAddress((void**)&wh1,    g_Wh1);
    cudaGetSymbolAddress((void**)&agg_ch, g_agg_ch);
    cudaGetSymbolAddress((void**)&agg_ge, g_agg_ge);
    cudaGetSymbolAddress((void**)&cnt,    g_cnt);
    cudaGetSymbolAddress((void**)&off,    g_off);
    cudaGetSymbolAddress((void**)&cur,    g_cur);
    cudaGetSymbolAddress((void**)&bsum,   g_bsum);
    cudaGetSymbolAddress((void**)&ebuf,   g_ebuf);
    cudaGetSymbolAddress((void**)&wt,     g_Wt);
    cudaGetSymbolAddress((void**)&abf,    g_Abf);

    cudaFuncSetAttribute(fused_gemm_agg,
                         cudaFuncAttributeMaxDynamicSharedMemorySize, SMEM_BYTES);

    const size_t NB = (size_t)NNODE * DIM;
    __nv_bfloat16* Ah[4];
    __nv_bfloat16* Al[4];
    for (int b = 0; b < 4; b++) {
        Ah[b] = abf + (size_t)(2 * b + 0) * NB;
        Al[b] = abf + (size_t)(2 * b + 1) * NB;
    }

    const int n4 = NNODE * DIM / 4;
    const int FULL = GEMM_BLOCKS + AGG_BLOCKS;

    // ---- build per-etype CSR ----
    zero_2i<<<(SCAN_N + 255) / 256, 256>>>(cnt, cur, SCAN_N);
    count_deg4<<<(4 * NE + 255) / 256, 256>>>(dst[0], dst[1], dst[2], dst[3], cnt);
    scan_p1<<<SCAN_BLKS, 256>>>(cnt, off, bsum);
    scan_p2<<<1, 256>>>(bsum);
    scan_p3<<<(SCAN_N + 255) / 256, 256>>>(off, bsum);
    scatter4<<<(4 * NE + 255) / 256, 256>>>(src[0], dst[0], src[1], dst[1],
                                            src[2], dst[2], src[3], dst[3],
                                            off, cur, ebuf);

    // ---- weight + embedding splits ----
    const float* wsrc[6] = {W1[0], W1[1], W1[2], W1[3], W2[1], W2[2]};
    for (int m = 0; m < 6; m++)
        split_w<<<256, 256>>>(wsrc[m], wt + (size_t)m * 131072,
                              wt + (size_t)m * 131072 + 65536);
    split_act<<<(n4 + 255) / 256, 256>>>(emb[0], Ah[0], Al[0], n4);
    split_act<<<(n4 + 255) / 256, 256>>>(emb[1], Ah[1], Al[1], n4);

    auto OFF = [&](int t) { return off + t * NNODE; };
    auto WT  = [&](int m) { return wt + (size_t)m * 131072; };

    // ===== pipeline: G(x) overlapped with A(prev) via block-role split =====
    // etypes: 0=ch2ge 1=ge2ch 2=ch2ch 3=ge2ge ; srcs: 0:ch 1:ge 2:ch 3:ge
    // 1: G0 (emb_ch x W1_0 -> wh0)
    fused_gemm_agg<<<GEMM_BLOCKS, 256, SMEM_BYTES>>>(
        Ah[0], Al[0], WT(0), WT(0) + 65536, b1[0], wh0, NNODE,
        nullptr, nullptr, nullptr, nullptr, nullptr, nullptr, 0, GEMM_BLOCKS);
    // 2: G3 (emb_ge x W1_3 -> wh1) | A0: wh0 -e0-> agg_ge WRITE
    fused_gemm_agg<<<FULL, 256, SMEM_BYTES>>>(
        Ah[1], Al[1], WT(3), WT(3) + 65536, b1[3], wh1, NNODE,
        OFF(0), ebuf, wh0, agg_ge, nullptr, nullptr, AGG_WRITE, GEMM_BLOCKS);
    // 3: G1 (emb_ge x W1_1 -> wh0) | A3: wh1 -e3-> agg_ge FINAL -> Ah[3]
    fused_gemm_agg<<<FULL, 256, SMEM_BYTES>>>(
        Ah[1], Al[1], WT(1), WT(1) + 65536, b1[1], wh0, NNODE,
        OFF(3), ebuf, wh1, agg_ge, Ah[3], Al[3], AGG_FINAL, GEMM_BLOCKS);
    // 4: G2 (emb_ch x W1_2 -> wh1) | A1: wh0 -e1-> agg_ch WRITE
    fused_gemm_agg<<<FULL, 256, SMEM_BYTES>>>(
        Ah[0], Al[0], WT(2), WT(2) + 65536, b1[2], wh1, NNODE,
        OFF(1), ebuf, wh0, agg_ch, nullptr, nullptr, AGG_WRITE, GEMM_BLOCKS);
    // 5: G4 (hid_ge x W2_ge2ch -> wh0) | A2: wh1 -e2-> agg_ch FINAL -> Ah[2]
    fused_gemm_agg<<<FULL, 256, SMEM_BYTES>>>(
        Ah[3], Al[3], WT(4), WT(4) + 65536, b2[1], wh0, NNODE,
        OFF(2), ebuf, wh1, agg_ch, Ah[2], Al[2], AGG_FINAL, GEMM_BLOCKS);
    // 6: G5 (hid_ch x W2_ch2ch -> wh1) | A4: wh0 -e1-> d_out WRITE
    fused_gemm_agg<<<FULL, 256, SMEM_BYTES>>>(
        Ah[2], Al[2], WT(5), WT(5) + 65536, b2[2], wh1, NNODE,
        OFF(1), ebuf, wh0, (float*)d_out, nullptr, nullptr, AGG_WRITE, GEMM_BLOCKS);
    // 7: A5: wh1 -e2-> d_out ACC (standalone, full occupancy)
    csr_agg<<<AGG_BLOCKS, 256>>>(OFF(2), ebuf, wh1, (float*)d_out,
                                 nullptr, nullptr, AGG_ACC);
}

// round 13
// speedup vs baseline: 1.3375x; 1.3375x over previous
#include <cuda_runtime.h>
#include <cuda_bf16.h>
#include <cstdint>

// ---------------------------------------------------------------------------
// Hetero-RGCN, 2 layers, output = chemical nodes.
// GEMM: mma.sync bf16 (HMMA) 3-term split, cp.async double-buffer + ldmatrix.
// Aggregation: CSR, standalone full-occupancy kernel, unroll-4 (MLP>=4),
//   modes WRITE / ACC / FINAL (FINAL fuses leaky-relu + bf16 hi/lo split).
// R13: fusion abandoned (R9+R12 both 1079us — smem-occupancy penalty is
//   structural); R10 serial skeleton + unroll-4 agg + AGG_FINAL.
// ---------------------------------------------------------------------------

#define NNODE 50000
#define DIM   256
#define NE    400000
#define SCAN_N (4 * NNODE)                   // 200000
#define SCAN_BLKS ((SCAN_N + 1023) / 1024)   // 196

#define AGG_BLOCKS 12500                     // 50000 nodes * 64 thr / 256

#define AGG_WRITE 0
#define AGG_ACC   1
#define AGG_FINAL 2

__device__ __align__(16) float g_Wh[NNODE * DIM];
__device__ __align__(16) float g_agg_ch[NNODE * DIM];
__device__ __align__(16) float g_agg_ge[NNODE * DIM];
__device__ __align__(16) int   g_cnt[SCAN_N];
__device__ __align__(16) int   g_off[SCAN_N + 1];
__device__ __align__(16) int   g_cur[SCAN_N];
__device__ __align__(16) int   g_bsum[SCAN_BLKS + 1];
__device__ __align__(16) int   g_ebuf[4 * NE];
__device__ __align__(16) __nv_bfloat16 g_Wt[6 * 2 * 65536];
__device__ __align__(16) __nv_bfloat16 g_Abf[4 * 2 * NNODE * DIM];

// ============================ small utility kernels =========================
__global__ void zero_2i(int* __restrict__ a, int* __restrict__ b, int n) {
    int i = blockIdx.x * blockDim.x + threadIdx.x;
    if (i < n) { a[i] = 0; b[i] = 0; }
}

__global__ void count_deg4(const int* __restrict__ d0, const int* __restrict__ d1,
                           const int* __restrict__ d2, const int* __restrict__ d3,
                           int* __restrict__ cnt) {
    int i = blockIdx.x * blockDim.x + threadIdx.x;
    if (i >= 4 * NE) return;
    int t = i / NE, e = i - t * NE;
    const int* d = (t == 0) ? d0 : (t == 1) ? d1 : (t == 2) ? d2 : d3;
    atomicAdd(&cnt[t * NNODE + d[e]], 1);
}

// ---- fast 3-pass exclusive scan over cnt[SCAN_N] -> off[SCAN_N+1] ----
__global__ __launch_bounds__(256)
void scan_p1(const int* __restrict__ cnt, int* __restrict__ off,
             int* __restrict__ bsum) {
    __shared__ int swarp[8];
    const int tid = threadIdx.x;
    const int lane = tid & 31, wrp = tid >> 5;
    const int i0 = blockIdx.x * 1024 + tid * 4;

    int v0 = 0, v1 = 0, v2 = 0, v3 = 0;
    if (i0 + 3 < SCAN_N) {
        int4 v = *reinterpret_cast<const int4*>(cnt + i0);
        v0 = v.x; v1 = v.y; v2 = v.z; v3 = v.w;
    } else {
        if (i0 + 0 < SCAN_N) v0 = cnt[i0 + 0];
        if (i0 + 1 < SCAN_N) v1 = cnt[i0 + 1];
        if (i0 + 2 < SCAN_N) v2 = cnt[i0 + 2];
        if (i0 + 3 < SCAN_N) v3 = cnt[i0 + 3];
    }
    int e1 = v0, e2 = v0 + v1, e3 = v0 + v1 + v2;
    int tsum = e3 + v3;

    int incl = tsum;
#pragma unroll
    for (int d = 1; d < 32; d <<= 1) {
        int u = __shfl_up_sync(0xffffffffu, incl, d);
        if (lane >= d) incl += u;
    }
    if (lane == 31) swarp[wrp] = incl;
    __syncthreads();
    if (wrp == 0 && lane < 8) {
        int w = swarp[lane];
        int wi = w;
#pragma unroll
        for (int d = 1; d < 8; d <<= 1) {
            int u = __shfl_up_sync(0xffu, wi, d);
            if (lane >= d) wi += u;
        }
        swarp[lane] = wi - w;
    }
    __syncthreads();
    int base = swarp[wrp] + (incl - tsum);

    if (i0 + 0 < SCAN_N) off[i0 + 0] = base;
    if (i0 + 1 < SCAN_N) off[i0 + 1] = base + e1;
    if (i0 + 2 < SCAN_N) off[i0 + 2] = base + e2;
    if (i0 + 3 < SCAN_N) off[i0 + 3] = base + e3;
    if (tid == 255) bsum[blockIdx.x] = base + tsum;
}

__global__ __launch_bounds__(256)
void scan_p2(int* __restrict__ bsum) {
    __shared__ int swarp[8];
    const int tid = threadIdx.x;
    const int lane = tid & 31, wrp = tid >> 5;
    int v = (tid < SCAN_BLKS) ? bsum[tid] : 0;
    int incl = v;
#pragma unroll
    for (int d = 1; d < 32; d <<= 1) {
        int u = __shfl_up_sync(0xffffffffu, incl, d);
        if (lane >= d) incl += u;
    }
    if (lane == 31) swarp[wrp] = incl;
    __syncthreads();
    if (wrp == 0 && lane < 8) {
        int w = swarp[lane];
        int wi = w;
#pragma unroll
        for (int d = 1; d < 8; d <<= 1) {
            int u = __shfl_up_sync(0xffu, wi, d);
            if (lane >= d) wi += u;
        }
        swarp[lane] = wi - w;
    }
    __syncthreads();
    if (tid < SCAN_BLKS) bsum[tid] = swarp[wrp] + (incl - v);
}

__global__ void scan_p3(int* __restrict__ off, const int* __restrict__ bsum) {
    int i = blockIdx.x * blockDim.x + threadIdx.x;
    if (i < SCAN_N) off[i] += bsum[i >> 10];
    if (i == 0) off[SCAN_N] = 4 * NE;
}

__global__ void scatter4(const int* __restrict__ s0, const int* __restrict__ d0,
                         const int* __restrict__ s1, const int* __restrict__ d1,
                         const int* __restrict__ s2, const int* __restrict__ d2,
                         const int* __restrict__ s3, const int* __restrict__ d3,
                         const int* __restrict__ off, int* __restrict__ cur,
                         int* __restrict__ ebuf) {
    int i = blockIdx.x * blockDim.x + threadIdx.x;
    if (i >= 4 * NE) return;
    int t = i / NE, e = i - t * NE;
    const int* s = (t == 0) ? s0 : (t == 1) ? s1 : (t == 2) ? s2 : s3;
    const int* d = (t == 0) ? d0 : (t == 1) ? d1 : (t == 2) ? d2 : d3;
    int dd = t * NNODE + d[e];
    int p = atomicAdd(&cur[dd], 1);
    ebuf[off[dd] + p] = s[e];
}

// Transpose + bf16 hi/lo split of one 256x256 weight: out[n][k] = W[k][n]
__global__ void split_w(const float* __restrict__ W,
                        __nv_bfloat16* __restrict__ hi,
                        __nv_bfloat16* __restrict__ lo) {
    int i = blockIdx.x * 256 + threadIdx.x;
    int n = i >> 8, k = i & 255;
    float w = W[k * 256 + n];
    __nv_bfloat16 h = __float2bfloat16_rn(w);
    hi[i] = h;
    lo[i] = __float2bfloat16_rn(w - __bfloat162float(h));
}

// fp32 activations -> bf16 hi/lo (input embeddings)
__global__ void split_act(const float* __restrict__ x,
                          __nv_bfloat16* __restrict__ hi,
                          __nv_bfloat16* __restrict__ lo, int n4) {
    int i = blockIdx.x * blockDim.x + threadIdx.x;
    if (i >= n4) return;
    float4 v = reinterpret_cast<const float4*>(x)[i];
    __nv_bfloat162 h01, h23, l01, l23;
    h01.x = __float2bfloat16_rn(v.x);
    h01.y = __float2bfloat16_rn(v.y);
    h23.x = __float2bfloat16_rn(v.z);
    h23.y = __float2bfloat16_rn(v.w);
    l01.x = __float2bfloat16_rn(v.x - __bfloat162float(h01.x));
    l01.y = __float2bfloat16_rn(v.y - __bfloat162float(h01.y));
    l23.x = __float2bfloat16_rn(v.z - __bfloat162float(h23.x));
    l23.y = __float2bfloat16_rn(v.w - __bfloat162float(h23.y));
    uint2 hv, lv;
    hv.x = *reinterpret_cast<uint32_t*>(&h01);
    hv.y = *reinterpret_cast<uint32_t*>(&h23);
    lv.x = *reinterpret_cast<uint32_t*>(&l01);
    lv.y = *reinterpret_cast<uint32_t*>(&l23);
    *reinterpret_cast<uint2*>(hi + (size_t)i * 4) = hv;
    *reinterpret_cast<uint2*>(lo + (size_t)i * 4) = lv;
}

// ====================== mma.sync bf16 split GEMM ============================
#define AST 40
#define STG_A_HI 0
#define STG_A_LO 10240
#define STG_B_HI 20480
#define STG_B_LO 30720
#define STG_BYTES 40960
#define SMEM_BYTES (2 * STG_BYTES)   // 81920

__device__ __forceinline__ uint32_t smem_u32(const void* p) {
    uint32_t a;
    asm("{ .reg .u64 t; cvta.to.shared.u64 t, %1; cvt.u32.u64 %0, t; }"
        : "=r"(a) : "l"(p));
    return a;
}

__device__ __forceinline__ void cp16(uint32_t s, const void* g, int sz) {
    asm volatile("cp.async.cg.shared.global [%0], [%1], 16, %2;"
                 :: "r"(s), "l"(g), "r"(sz));
}

__device__ __forceinline__ void ldm_x4(uint32_t* r, uint32_t addr) {
    asm volatile("ldmatrix.sync.aligned.m8n8.x4.shared.b16 {%0,%1,%2,%3}, [%4];"
                 : "=r"(r[0]), "=r"(r[1]), "=r"(r[2]), "=r"(r[3]) : "r"(addr));
}

__device__ __forceinline__ void mma_bf16(float* c, const uint32_t* a,
                                         const uint32_t* b) {
    asm volatile(
        "mma.sync.aligned.m16n8k16.row.col.f32.bf16.bf16.f32 "
        "{%0,%1,%2,%3}, {%4,%5,%6,%7}, {%8,%9}, {%0,%1,%2,%3};"
        : "+f"(c[0]), "+f"(c[1]), "+f"(c[2]), "+f"(c[3])
        : "r"(a[0]), "r"(a[1]), "r"(a[2]), "r"(a[3]), "r"(b[0]), "r"(b[1]));
}

__global__ __launch_bounds__(256, 2)
void gemm_mma(const __nv_bfloat16* __restrict__ Ahi,
              const __nv_bfloat16* __restrict__ Alo,
              const __nv_bfloat16* __restrict__ Bhi,
              const __nv_bfloat16* __restrict__ Blo,
              const float* __restrict__ bias,
              float* __restrict__ C, int M)
{
    extern __shared__ char smc[];
    const uint32_t smb = smem_u32(smc);

    const int tid = threadIdx.x;
    const int wid = tid >> 5;
    const int lid = tid & 31;
    const int wr = wid & 1;
    const int wc = wid >> 1;
    const int g = lid >> 2;
    const int t = lid & 3;
    const int row0 = blockIdx.y * 128;
    const int col0 = blockIdx.x * 128;

    const int a_row_l = wr * 64 + (lid & 7) + ((lid >> 3) & 1) * 8;
    const int a_col_l = ((lid >> 4) & 1) * 8;
    const int b_row_l = wc * 32 + (lid & 7) + ((lid >> 4) & 1) * 8;
    const int b_col_l = ((lid >> 3) & 1) * 8;

    float acc[4][4][4];
#pragma unroll
    for (int i = 0; i < 4; i++)
#pragma unroll
        for (int j = 0; j < 4; j++)
#pragma unroll
            for (int k = 0; k < 4; k++) acc[i][j][k] = 0.f;

#define ISSUE_STAGE(stage, k0)                                                 \
    do {                                                                       \
        uint32_t sb = smb + (stage) * STG_BYTES;                               \
        _Pragma("unroll")                                                      \
        for (int it = 0; it < 2; ++it) {                                       \
            int i = it * 256 + tid;                                            \
            int r = i >> 2, ch = i & 3;                                        \
            uint32_t so = (uint32_t)(r * 80 + ch * 16);                        \
            int gr = row0 + r;                                                 \
            int sz = (gr < M) ? 16 : 0;                                        \
            size_t aoff = (size_t)(gr < M ? gr : 0) * 256 + (k0) + ch * 8;     \
            cp16(sb + STG_A_HI + so, Ahi + aoff, sz);                          \
            cp16(sb + STG_A_LO + so, Alo + aoff, sz);                          \
            size_t boff = (size_t)(col0 + r) * 256 + (k0) + ch * 8;            \
            cp16(sb + STG_B_HI + so, Bhi + boff, 16);                          \
            cp16(sb + STG_B_LO + so, Blo + boff, 16);                          \
        }                                                                      \
        asm volatile("cp.async.commit_group;" ::: "memory");                   \
    } while (0)

    ISSUE_STAGE(0, 0);

    for (int kb = 0; kb < 8; ++kb) {
        const int st = kb & 1;
        if (kb < 7) {
            ISSUE_STAGE(st ^ 1, (kb + 1) * 32);
            asm volatile("cp.async.wait_group 1;" ::: "memory");
        } else {
            asm volatile("cp.async.wait_group 0;" ::: "memory");
        }
        __syncthreads();

        const uint32_t stg = smb + st * STG_BYTES;

#pragma unroll
        for (int ks = 0; ks < 2; ++ks) {
            const int kk = ks * 16;
            uint32_t af[4][4], bh[2][4], bl[2][4];

#pragma unroll
            for (int np = 0; np < 2; ++np) {
                uint32_t boff = (uint32_t)((b_row_l + np * 16) * AST + kk + b_col_l) * 2;
                ldm_x4(bh[np], stg + STG_B_HI + boff);
                ldm_x4(bl[np], stg + STG_B_LO + boff);
            }
#pragma unroll
            for (int mt = 0; mt < 4; ++mt) {
                uint32_t aoff = (uint32_t)((a_row_l + mt * 16) * AST + kk + a_col_l) * 2;
                ldm_x4(af[mt], stg + STG_A_HI + aoff);
            }
#pragma unroll
            for (int mt = 0; mt < 4; ++mt)
#pragma unroll
                for (int nt = 0; nt < 4; ++nt)
                    mma_bf16(acc[mt][nt], af[mt], &bh[nt >> 1][(nt & 1) * 2]);
#pragma unroll
            for (int mt = 0; mt < 4; ++mt)
#pragma unroll
                for (int nt = 0; nt < 4; ++nt)
                    mma_bf16(acc[mt][nt], af[mt], &bl[nt >> 1][(nt & 1) * 2]);
#pragma unroll
            for (int mt = 0; mt < 4; ++mt) {
                uint32_t aoff = (uint32_t)((a_row_l + mt * 16) * AST + kk + a_col_l) * 2;
                ldm_x4(af[mt], stg + STG_A_LO + aoff);
            }
#pragma unroll
            for (int mt = 0; mt < 4; ++mt)
#pragma unroll
                for (int nt = 0; nt < 4; ++nt)
                    mma_bf16(acc[mt][nt], af[mt], &bh[nt >> 1][(nt & 1) * 2]);
        }
        __syncthreads();
    }

#pragma unroll
    for (int nt = 0; nt < 4; ++nt) {
        const int gc = col0 + wc * 32 + nt * 8 + t * 2;
        float2 bb = *reinterpret_cast<const float2*>(bias + gc);
#pragma unroll
        for (int mt = 0; mt < 4; ++mt) {
            int r0 = row0 + wr * 64 + mt * 16 + g;
            if (r0 < M) {
                float2 o;
                o.x = acc[mt][nt][0] + bb.x;
                o.y = acc[mt][nt][1] + bb.y;
                *reinterpret_cast<float2*>(C + (size_t)r0 * 256 + gc) = o;
            }
            if (r0 + 8 < M) {
                float2 o;
                o.x = acc[mt][nt][2] + bb.x;
                o.y = acc[mt][nt][3] + bb.y;
                *reinterpret_cast<float2*>(C + (size_t)(r0 + 8) * 256 + gc) = o;
            }
        }
    }
}

// ============== CSR mean aggregation (unroll-4, 3 modes) ===================
// 64 threads per dst node; FINAL mode fuses leaky-relu + bf16 hi/lo split.
__global__ void csr_agg(const int* __restrict__ off, const int* __restrict__ ebuf,
                        const float* __restrict__ Wh, float* __restrict__ agg,
                        __nv_bfloat16* __restrict__ hi,
                        __nv_bfloat16* __restrict__ lo, int mode)
{
    int idx = blockIdx.x * blockDim.x + threadIdx.x;
    int node = idx >> 6;
    if (node >= NNODE) return;
    int q = (idx & 63) << 2;
    int e0 = __ldg(off + node), e1 = __ldg(off + node + 1);

    float4 s = make_float4(0.f, 0.f, 0.f, 0.f);
    int e = e0;
    for (; e + 4 <= e1; e += 4) {
        int i0 = __ldg(ebuf + e + 0);
        int i1 = __ldg(ebuf + e + 1);
        int i2 = __ldg(ebuf + e + 2);
        int i3 = __ldg(ebuf + e + 3);
        float4 v0 = *reinterpret_cast<const float4*>(Wh + (size_t)i0 * DIM + q);
        float4 v1 = *reinterpret_cast<const float4*>(Wh + (size_t)i1 * DIM + q);
        float4 v2 = *reinterpret_cast<const float4*>(Wh + (size_t)i2 * DIM + q);
        float4 v3 = *reinterpret_cast<const float4*>(Wh + (size_t)i3 * DIM + q);
        s.x += (v0.x + v1.x) + (v2.x + v3.x);
        s.y += (v0.y + v1.y) + (v2.y + v3.y);
        s.z += (v0.z + v1.z) + (v2.z + v3.z);
        s.w += (v0.w + v1.w) + (v2.w + v3.w);
    }
    for (; e < e1; ++e) {
        int si = __ldg(ebuf + e);
        float4 v = *reinterpret_cast<const float4*>(Wh + (size_t)si * DIM + q);
        s.x += v.x; s.y += v.y; s.z += v.z; s.w += v.w;
    }
    float w = (e1 > e0) ? 1.0f / (float)(e1 - e0) : 0.f;
    s.x *= w; s.y *= w; s.z *= w; s.w *= w;

    if (mode == AGG_WRITE) {
        *reinterpret_cast<float4*>(agg + (size_t)node * DIM + q) = s;
    } else if (mode == AGG_ACC) {
        if (e0 == e1) return;
        float4* out = reinterpret_cast<float4*>(agg + (size_t)node * DIM + q);
        float4 a = *out;
        a.x += s.x; a.y += s.y; a.z += s.z; a.w += s.w;
        *out = a;
    } else {  // AGG_FINAL: prev + s, leaky-relu, bf16 hi/lo split
        float4 a = *reinterpret_cast<const float4*>(agg + (size_t)node * DIM + q);
        a.x += s.x; a.y += s.y; a.z += s.z; a.w += s.w;
        a.x = a.x > 0.f ? a.x : 0.01f * a.x;
        a.y = a.y > 0.f ? a.y : 0.01f * a.y;
        a.z = a.z > 0.f ? a.z : 0.01f * a.z;
        a.w = a.w > 0.f ? a.w : 0.01f * a.w;
        __nv_bfloat162 h01, h23, l01, l23;
        h01.x = __float2bfloat16_rn(a.x);
        h01.y = __float2bfloat16_rn(a.y);
        h23.x = __float2bfloat16_rn(a.z);
        h23.y = __float2bfloat16_rn(a.w);
        l01.x = __float2bfloat16_rn(a.x - __bfloat162float(h01.x));
        l01.y = __float2bfloat16_rn(a.y - __bfloat162float(h01.y));
        l23.x = __float2bfloat16_rn(a.z - __bfloat162float(h23.x));
        l23.y = __float2bfloat16_rn(a.w - __bfloat162float(h23.y));
        uint2 hv, lv;
        hv.x = *reinterpret_cast<uint32_t*>(&h01);
        hv.y = *reinterpret_cast<uint32_t*>(&h23);
        lv.x = *reinterpret_cast<uint32_t*>(&l01);
        lv.y = *reinterpret_cast<uint32_t*>(&l23);
        *reinterpret_cast<uint2*>(hi + (size_t)node * DIM + q) = hv;
        *reinterpret_cast<uint2*>(lo + (size_t)node * DIM + q) = lv;
    }
}

// --------------------------------------------------------------------- host
extern "C" void kernel_launch(void* const* d_in, const int* in_sizes, int n_in,
                              void* d_out, int out_size)
{
    (void)n_in; (void)out_size;

    const float* emb[2] = {(const float*)d_in[0], (const float*)d_in[1]};
    const float *W1[4], *b1[4], *W2[4], *b2[4];
    const int *src[4], *dst[4];

    bool dict_order = (in_sizes[6] == NE);
    if (dict_order) {
        for (int t = 0; t < 4; t++) {
            const int base = 2 + 6 * t;
            W1[t]  = (const float*)d_in[base + 0];
            b1[t]  = (const float*)d_in[base + 1];
            W2[t]  = (const float*)d_in[base + 2];
            b2[t]  = (const float*)d_in[base + 3];
            src[t] = (const int*)  d_in[base + 4];
            dst[t] = (const int*)  d_in[base + 5];
        }
    } else {
        for (int t = 0; t < 4; t++) {
            W1[t]  = (const float*)d_in[2  + 2 * t];
            b1[t]  = (const float*)d_in[3  + 2 * t];
            W2[t]  = (const float*)d_in[10 + 2 * t];
            b2[t]  = (const float*)d_in[11 + 2 * t];
            src[t] = (const int*)  d_in[18 + 2 * t];
            dst[t] = (const int*)  d_in[19 + 2 * t];
        }
    }

    float *wh, *agg_ch, *agg_ge;
    int *cnt, *off, *cur, *bsum, *ebuf;
    __nv_bfloat16 *wt, *abf;
    cudaGetSymbolAddress((void**)&wh,     g_Wh);
    cudaGetSymbolAddress((void**)&agg_ch, g_agg_ch);
    cudaGetSymbolAddress((void**)&agg_ge, g_agg_ge);
    cudaGetSymbolAddress((void**)&cnt,    g_cnt);
    cudaGetSymbolAddress((void**)&off,    g_off);
    cudaGetSymbolAddress((void**)&cur,    g_cur);
    cudaGetSymbolAddress((void**)&bsum,   g_bsum);
    cudaGetSymbolAddress((void**)&ebuf,   g_ebuf);
    cudaGetSymbolAddress((void**)&wt,     g_Wt);
    cudaGetSymbolAddress((void**)&abf,    g_Abf);

    cudaFuncSetAttribute(gemm_mma, cudaFuncAttributeMaxDynamicSharedMemorySize,
                         SMEM_BYTES);

    const size_t NB = (size_t)NNODE * DIM;
    __nv_bfloat16* Ah[4];
    __nv_bfloat16* Al[4];
    for (int b = 0; b < 4; b++) {
        Ah[b] = abf + (size_t)(2 * b + 0) * NB;
        Al[b] = abf + (size_t)(2 * b + 1) * NB;
    }

    const int n4 = NNODE * DIM / 4;
    dim3 ggrid(2, (NNODE + 127) / 128);

    // ---- build per-etype CSR ----
    zero_2i<<<(SCAN_N + 255) / 256, 256>>>(cnt, cur, SCAN_N);
    count_deg4<<<(4 * NE + 255) / 256, 256>>>(dst[0], dst[1], dst[2], dst[3], cnt);
    scan_p1<<<SCAN_BLKS, 256>>>(cnt, off, bsum);
    scan_p2<<<1, 256>>>(bsum);
    scan_p3<<<(SCAN_N + 255) / 256, 256>>>(off, bsum);
    scatter4<<<(4 * NE + 255) / 256, 256>>>(src[0], dst[0], src[1], dst[1],
                                            src[2], dst[2], src[3], dst[3],
                                            off, cur, ebuf);

    // ---- weight + embedding splits ----
    const float* wsrc[6] = {W1[0], W1[1], W1[2], W1[3], W2[1], W2[2]};
    for (int m = 0; m < 6; m++)
        split_w<<<256, 256>>>(wsrc[m], wt + (size_t)m * 131072,
                              wt + (size_t)m * 131072 + 65536);
    split_act<<<(n4 + 255) / 256, 256>>>(emb[0], Ah[0], Al[0], n4);
    split_act<<<(n4 + 255) / 256, 256>>>(emb[1], Ah[1], Al[1], n4);

    auto OFF = [&](int t) { return off + t * NNODE; };
    auto WT  = [&](int m) { return wt + (size_t)m * 131072; };

    // -------- layer 1, order 0 -> 1 -> 3 -> 2 so last agg per buffer is FINAL
    // etypes: 0=ch2ge(src ch,dst ge) 1=ge2ch 2=ch2ch 3=ge2ge
    // t=0: emb_ch x W1_0 -> agg_ge WRITE
    gemm_mma<<<ggrid, 256, SMEM_BYTES>>>(Ah[0], Al[0], WT(0), WT(0) + 65536,
                                         b1[0], wh, NNODE);
    csr_agg<<<AGG_BLOCKS, 256>>>(OFF(0), ebuf, wh, agg_ge,
                                 nullptr, nullptr, AGG_WRITE);
    // t=1: emb_ge x W1_1 -> agg_ch WRITE
    gemm_mma<<<ggrid, 256, SMEM_BYTES>>>(Ah[1], Al[1], WT(1), WT(1) + 65536,
                                         b1[1], wh, NNODE);
    csr_agg<<<AGG_BLOCKS, 256>>>(OFF(1), ebuf, wh, agg_ch,
                                 nullptr, nullptr, AGG_WRITE);
    // t=3: emb_ge x W1_3 -> agg_ge FINAL -> Ah[3]/Al[3]
    gemm_mma<<<ggrid, 256, SMEM_BYTES>>>(Ah[1], Al[1], WT(3), WT(3) + 65536,
                                         b1[3], wh, NNODE);
    csr_agg<<<AGG_BLOCKS, 256>>>(OFF(3), ebuf, wh, agg_ge,
                                 Ah[3], Al[3], AGG_FINAL);
    // t=2: emb_ch x W1_2 -> agg_ch FINAL -> Ah[2]/Al[2]
    gemm_mma<<<ggrid, 256, SMEM_BYTES>>>(Ah[0], Al[0], WT(2), WT(2) + 65536,
                                         b1[2], wh, NNODE);
    csr_agg<<<AGG_BLOCKS, 256>>>(OFF(2), ebuf, wh, agg_ch,
                                 Ah[2], Al[2], AGG_FINAL);

    // -------- layer 2: only dst==chemical etypes (ge2ch=1, ch2ch=2) --------
    gemm_mma<<<ggrid, 256, SMEM_BYTES>>>(Ah[3], Al[3], WT(4), WT(4) + 65536,
                                         b2[1], wh, NNODE);
    csr_agg<<<AGG_BLOCKS, 256>>>(OFF(1), ebuf, wh, (float*)d_out,
                                 nullptr, nullptr, AGG_WRITE);
    gemm_mma<<<ggrid, 256, SMEM_BYTES>>>(Ah[2], Al[2], WT(5), WT(5) + 65536,
                                         b2[2], wh, NNODE);
    csr_agg<<<AGG_BLOCKS, 256>>>(OFF(2), ebuf, wh, (float*)d_out,
                                 nullptr, nullptr, AGG_ACC);
}

// round 14
// speedup vs baseline: 1.3605x; 1.0172x over previous
#include <cuda_runtime.h>
#include <cuda_bf16.h>
#include <cstdint>

// ---------------------------------------------------------------------------
// Hetero-RGCN, 2 layers, output = chemical nodes.
// GEMM: mma.sync bf16 (HMMA) 3-term split, cp.async double-buffer + ldmatrix.
// Aggregation: CSR, unroll-4, modes WRITE/ACC/FINAL (FINAL fuses lrelu+split).
// R14: TRUE GEMM||AGG overlap via a second stream + fork-join events inside
//   graph capture (separate kernels keep their own occupancy configs, unlike
//   the failed single-kernel role-split). wh ping-pong decouples G(t+1)/A(t).
// ---------------------------------------------------------------------------

#define NNODE 50000
#define DIM   256
#define NE    400000
#define SCAN_N (4 * NNODE)                   // 200000
#define SCAN_BLKS ((SCAN_N + 1023) / 1024)   // 196

#define AGG_BLOCKS 12500                     // 50000 nodes * 64 thr / 256

#define AGG_WRITE 0
#define AGG_ACC   1
#define AGG_FINAL 2

__device__ __align__(16) float g_Wh0[NNODE * DIM];
__device__ __align__(16) float g_Wh1[NNODE * DIM];
__device__ __align__(16) float g_agg_ch[NNODE * DIM];
__device__ __align__(16) float g_agg_ge[NNODE * DIM];
__device__ __align__(16) int   g_cnt[SCAN_N];
__device__ __align__(16) int   g_off[SCAN_N + 1];
__device__ __align__(16) int   g_cur[SCAN_N];
__device__ __align__(16) int   g_bsum[SCAN_BLKS + 1];
__device__ __align__(16) int   g_ebuf[4 * NE];
__device__ __align__(16) __nv_bfloat16 g_Wt[6 * 2 * 65536];
__device__ __align__(16) __nv_bfloat16 g_Abf[4 * 2 * NNODE * DIM];

// ============================ small utility kernels =========================
__global__ void zero_2i(int* __restrict__ a, int* __restrict__ b, int n) {
    int i = blockIdx.x * blockDim.x + threadIdx.x;
    if (i < n) { a[i] = 0; b[i] = 0; }
}

__global__ void count_deg4(const int* __restrict__ d0, const int* __restrict__ d1,
                           const int* __restrict__ d2, const int* __restrict__ d3,
                           int* __restrict__ cnt) {
    int i = blockIdx.x * blockDim.x + threadIdx.x;
    if (i >= 4 * NE) return;
    int t = i / NE, e = i - t * NE;
    const int* d = (t == 0) ? d0 : (t == 1) ? d1 : (t == 2) ? d2 : d3;
    atomicAdd(&cnt[t * NNODE + d[e]], 1);
}

// ---- fast 3-pass exclusive scan over cnt[SCAN_N] -> off[SCAN_N+1] ----
__global__ __launch_bounds__(256)
void scan_p1(const int* __restrict__ cnt, int* __restrict__ off,
             int* __restrict__ bsum) {
    __shared__ int swarp[8];
    const int tid = threadIdx.x;
    const int lane = tid & 31, wrp = tid >> 5;
    const int i0 = blockIdx.x * 1024 + tid * 4;

    int v0 = 0, v1 = 0, v2 = 0, v3 = 0;
    if (i0 + 3 < SCAN_N) {
        int4 v = *reinterpret_cast<const int4*>(cnt + i0);
        v0 = v.x; v1 = v.y; v2 = v.z; v3 = v.w;
    } else {
        if (i0 + 0 < SCAN_N) v0 = cnt[i0 + 0];
        if (i0 + 1 < SCAN_N) v1 = cnt[i0 + 1];
        if (i0 + 2 < SCAN_N) v2 = cnt[i0 + 2];
        if (i0 + 3 < SCAN_N) v3 = cnt[i0 + 3];
    }
    int e1 = v0, e2 = v0 + v1, e3 = v0 + v1 + v2;
    int tsum = e3 + v3;

    int incl = tsum;
#pragma unroll
    for (int d = 1; d < 32; d <<= 1) {
        int u = __shfl_up_sync(0xffffffffu, incl, d);
        if (lane >= d) incl += u;
    }
    if (lane == 31) swarp[wrp] = incl;
    __syncthreads();
    if (wrp == 0 && lane < 8) {
        int w = swarp[lane];
        int wi = w;
#pragma unroll
        for (int d = 1; d < 8; d <<= 1) {
            int u = __shfl_up_sync(0xffu, wi, d);
            if (lane >= d) wi += u;
        }
        swarp[lane] = wi - w;
    }
    __syncthreads();
    int base = swarp[wrp] + (incl - tsum);

    if (i0 + 0 < SCAN_N) off[i0 + 0] = base;
    if (i0 + 1 < SCAN_N) off[i0 + 1] = base + e1;
    if (i0 + 2 < SCAN_N) off[i0 + 2] = base + e2;
    if (i0 + 3 < SCAN_N) off[i0 + 3] = base + e3;
    if (tid == 255) bsum[blockIdx.x] = base + tsum;
}

__global__ __launch_bounds__(256)
void scan_p2(int* __restrict__ bsum) {
    __shared__ int swarp[8];
    const int tid = threadIdx.x;
    const int lane = tid & 31, wrp = tid >> 5;
    int v = (tid < SCAN_BLKS) ? bsum[tid] : 0;
    int incl = v;
#pragma unroll
    for (int d = 1; d < 32; d <<= 1) {
        int u = __shfl_up_sync(0xffffffffu, incl, d);
        if (lane >= d) incl += u;
    }
    if (lane == 31) swarp[wrp] = incl;
    __syncthreads();
    if (wrp == 0 && lane < 8) {
        int w = swarp[lane];
        int wi = w;
#pragma unroll
        for (int d = 1; d < 8; d <<= 1) {
            int u = __shfl_up_sync(0xffu, wi, d);
            if (lane >= d) wi += u;
        }
        swarp[lane] = wi - w;
    }
    __syncthreads();
    if (tid < SCAN_BLKS) bsum[tid] = swarp[wrp] + (incl - v);
}

__global__ void scan_p3(int* __restrict__ off, const int* __restrict__ bsum) {
    int i = blockIdx.x * blockDim.x + threadIdx.x;
    if (i < SCAN_N) off[i] += bsum[i >> 10];
    if (i == 0) off[SCAN_N] = 4 * NE;
}

__global__ void scatter4(const int* __restrict__ s0, const int* __restrict__ d0,
                         const int* __restrict__ s1, const int* __restrict__ d1,
                         const int* __restrict__ s2, const int* __restrict__ d2,
                         const int* __restrict__ s3, const int* __restrict__ d3,
                         const int* __restrict__ off, int* __restrict__ cur,
                         int* __restrict__ ebuf) {
    int i = blockIdx.x * blockDim.x + threadIdx.x;
    if (i >= 4 * NE) return;
    int t = i / NE, e = i - t * NE;
    const int* s = (t == 0) ? s0 : (t == 1) ? s1 : (t == 2) ? s2 : s3;
    const int* d = (t == 0) ? d0 : (t == 1) ? d1 : (t == 2) ? d2 : d3;
    int dd = t * NNODE + d[e];
    int p = atomicAdd(&cur[dd], 1);
    ebuf[off[dd] + p] = s[e];
}

// Transpose + bf16 hi/lo split of one 256x256 weight: out[n][k] = W[k][n]
__global__ void split_w(const float* __restrict__ W,
                        __nv_bfloat16* __restrict__ hi,
                        __nv_bfloat16* __restrict__ lo) {
    int i = blockIdx.x * 256 + threadIdx.x;
    int n = i >> 8, k = i & 255;
    float w = W[k * 256 + n];
    __nv_bfloat16 h = __float2bfloat16_rn(w);
    hi[i] = h;
    lo[i] = __float2bfloat16_rn(w - __bfloat162float(h));
}

// fp32 activations -> bf16 hi/lo (input embeddings)
__global__ void split_act(const float* __restrict__ x,
                          __nv_bfloat16* __restrict__ hi,
                          __nv_bfloat16* __restrict__ lo, int n4) {
    int i = blockIdx.x * blockDim.x + threadIdx.x;
    if (i >= n4) return;
    float4 v = reinterpret_cast<const float4*>(x)[i];
    __nv_bfloat162 h01, h23, l01, l23;
    h01.x = __float2bfloat16_rn(v.x);
    h01.y = __float2bfloat16_rn(v.y);
    h23.x = __float2bfloat16_rn(v.z);
    h23.y = __float2bfloat16_rn(v.w);
    l01.x = __float2bfloat16_rn(v.x - __bfloat162float(h01.x));
    l01.y = __float2bfloat16_rn(v.y - __bfloat162float(h01.y));
    l23.x = __float2bfloat16_rn(v.z - __bfloat162float(h23.x));
    l23.y = __float2bfloat16_rn(v.w - __bfloat162float(h23.y));
    uint2 hv, lv;
    hv.x = *reinterpret_cast<uint32_t*>(&h01);
    hv.y = *reinterpret_cast<uint32_t*>(&h23);
    lv.x = *reinterpret_cast<uint32_t*>(&l01);
    lv.y = *reinterpret_cast<uint32_t*>(&l23);
    *reinterpret_cast<uint2*>(hi + (size_t)i * 4) = hv;
    *reinterpret_cast<uint2*>(lo + (size_t)i * 4) = lv;
}

// ====================== mma.sync bf16 split GEMM ============================
#define AST 40
#define STG_A_HI 0
#define STG_A_LO 10240
#define STG_B_HI 20480
#define STG_B_LO 30720
#define STG_BYTES 40960
#define SMEM_BYTES (2 * STG_BYTES)   // 81920

__device__ __forceinline__ uint32_t smem_u32(const void* p) {
    uint32_t a;
    asm("{ .reg .u64 t; cvta.to.shared.u64 t, %1; cvt.u32.u64 %0, t; }"
        : "=r"(a) : "l"(p));
    return a;
}

__device__ __forceinline__ void cp16(uint32_t s, const void* g, int sz) {
    asm volatile("cp.async.cg.shared.global [%0], [%1], 16, %2;"
                 :: "r"(s), "l"(g), "r"(sz));
}

__device__ __forceinline__ void ldm_x4(uint32_t* r, uint32_t addr) {
    asm volatile("ldmatrix.sync.aligned.m8n8.x4.shared.b16 {%0,%1,%2,%3}, [%4];"
                 : "=r"(r[0]), "=r"(r[1]), "=r"(r[2]), "=r"(r[3]) : "r"(addr));
}

__device__ __forceinline__ void mma_bf16(float* c, const uint32_t* a,
                                         const uint32_t* b) {
    asm volatile(
        "mma.sync.aligned.m16n8k16.row.col.f32.bf16.bf16.f32 "
        "{%0,%1,%2,%3}, {%4,%5,%6,%7}, {%8,%9}, {%0,%1,%2,%3};"
        : "+f"(c[0]), "+f"(c[1]), "+f"(c[2]), "+f"(c[3])
        : "r"(a[0]), "r"(a[1]), "r"(a[2]), "r"(a[3]), "r"(b[0]), "r"(b[1]));
}

__global__ __launch_bounds__(256, 2)
void gemm_mma(const __nv_bfloat16* __restrict__ Ahi,
              const __nv_bfloat16* __restrict__ Alo,
              const __nv_bfloat16* __restrict__ Bhi,
              const __nv_bfloat16* __restrict__ Blo,
              const float* __restrict__ bias,
              float* __restrict__ C, int M)
{
    extern __shared__ char smc[];
    const uint32_t smb = smem_u32(smc);

    const int tid = threadIdx.x;
    const int wid = tid >> 5;
    const int lid = tid & 31;
    const int wr = wid & 1;
    const int wc = wid >> 1;
    const int g = lid >> 2;
    const int t = lid & 3;
    const int row0 = blockIdx.y * 128;
    const int col0 = blockIdx.x * 128;

    const int a_row_l = wr * 64 + (lid & 7) + ((lid >> 3) & 1) * 8;
    const int a_col_l = ((lid >> 4) & 1) * 8;
    const int b_row_l = wc * 32 + (lid & 7) + ((lid >> 4) & 1) * 8;
    const int b_col_l = ((lid >> 3) & 1) * 8;

    float acc[4][4][4];
#pragma unroll
    for (int i = 0; i < 4; i++)
#pragma unroll
        for (int j = 0; j < 4; j++)
#pragma unroll
            for (int k = 0; k < 4; k++) acc[i][j][k] = 0.f;

#define ISSUE_STAGE(stage, k0)                                                 \
    do {                                                                       \
        uint32_t sb = smb + (stage) * STG_BYTES;                               \
        _Pragma("unroll")                                                      \
        for (int it = 0; it < 2; ++it) {                                       \
            int i = it * 256 + tid;                                            \
            int r = i >> 2, ch = i & 3;                                        \
            uint32_t so = (uint32_t)(r * 80 + ch * 16);                        \
            int gr = row0 + r;                                                 \
            int sz = (gr < M) ? 16 : 0;                                        \
            size_t aoff = (size_t)(gr < M ? gr : 0) * 256 + (k0) + ch * 8;     \
            cp16(sb + STG_A_HI + so, Ahi + aoff, sz);                          \
            cp16(sb + STG_A_LO + so, Alo + aoff, sz);                          \
            size_t boff = (size_t)(col0 + r) * 256 + (k0) + ch * 8;            \
            cp16(sb + STG_B_HI + so, Bhi + boff, 16);                          \
            cp16(sb + STG_B_LO + so, Blo + boff, 16);                          \
        }                                                                      \
        asm volatile("cp.async.commit_group;" ::: "memory");                   \
    } while (0)

    ISSUE_STAGE(0, 0);

    for (int kb = 0; kb < 8; ++kb) {
        const int st = kb & 1;
        if (kb < 7) {
            ISSUE_STAGE(st ^ 1, (kb + 1) * 32);
            asm volatile("cp.async.wait_group 1;" ::: "memory");
        } else {
            asm volatile("cp.async.wait_group 0;" ::: "memory");
        }
        __syncthreads();

        const uint32_t stg = smb + st * STG_BYTES;

#pragma unroll
        for (int ks = 0; ks < 2; ++ks) {
            const int kk = ks * 16;
            uint32_t af[4][4], bh[2][4], bl[2][4];

#pragma unroll
            for (int np = 0; np < 2; ++np) {
                uint32_t boff = (uint32_t)((b_row_l + np * 16) * AST + kk + b_col_l) * 2;
                ldm_x4(bh[np], stg + STG_B_HI + boff);
                ldm_x4(bl[np], stg + STG_B_LO + boff);
            }
#pragma unroll
            for (int mt = 0; mt < 4; ++mt) {
                uint32_t aoff = (uint32_t)((a_row_l + mt * 16) * AST + kk + a_col_l) * 2;
                ldm_x4(af[mt], stg + STG_A_HI + aoff);
            }
#pragma unroll
            for (int mt = 0; mt < 4; ++mt)
#pragma unroll
                for (int nt = 0; nt < 4; ++nt)
                    mma_bf16(acc[mt][nt], af[mt], &bh[nt >> 1][(nt & 1) * 2]);
#pragma unroll
            for (int mt = 0; mt < 4; ++mt)
#pragma unroll
                for (int nt = 0; nt < 4; ++nt)
                    mma_bf16(acc[mt][nt], af[mt], &bl[nt >> 1][(nt & 1) * 2]);
#pragma unroll
            for (int mt = 0; mt < 4; ++mt) {
                uint32_t aoff = (uint32_t)((a_row_l + mt * 16) * AST + kk + a_col_l) * 2;
                ldm_x4(af[mt], stg + STG_A_LO + aoff);
            }
#pragma unroll
            for (int mt = 0; mt < 4; ++mt)
#pragma unroll
                for (int nt = 0; nt < 4; ++nt)
                    mma_bf16(acc[mt][nt], af[mt], &bh[nt >> 1][(nt & 1) * 2]);
        }
        __syncthreads();
    }

#pragma unroll
    for (int nt = 0; nt < 4; ++nt) {
        const int gc = col0 + wc * 32 + nt * 8 + t * 2;
        float2 bb = *reinterpret_cast<const float2*>(bias + gc);
#pragma unroll
        for (int mt = 0; mt < 4; ++mt) {
            int r0 = row0 + wr * 64 + mt * 16 + g;
            if (r0 < M) {
                float2 o;
                o.x = acc[mt][nt][0] + bb.x;
                o.y = acc[mt][nt][1] + bb.y;
                *reinterpret_cast<float2*>(C + (size_t)r0 * 256 + gc) = o;
            }
            if (r0 + 8 < M) {
                float2 o;
                o.x = acc[mt][nt][2] + bb.x;
                o.y = acc[mt][nt][3] + bb.y;
                *reinterpret_cast<float2*>(C + (size_t)(r0 + 8) * 256 + gc) = o;
            }
        }
    }
}

// ============== CSR mean aggregation (unroll-4, 3 modes) ===================
__global__ void csr_agg(const int* __restrict__ off, const int* __restrict__ ebuf,
                        const float* __restrict__ Wh, float* __restrict__ agg,
                        __nv_bfloat16* __restrict__ hi,
                        __nv_bfloat16* __restrict__ lo, int mode)
{
    int idx = blockIdx.x * blockDim.x + threadIdx.x;
    int node = idx >> 6;
    if (node >= NNODE) return;
    int q = (idx & 63) << 2;
    int e0 = __ldg(off + node), e1 = __ldg(off + node + 1);

    float4 s = make_float4(0.f, 0.f, 0.f, 0.f);
    int e = e0;
    for (; e + 4 <= e1; e += 4) {
        int i0 = __ldg(ebuf + e + 0);
        int i1 = __ldg(ebuf + e + 1);
        int i2 = __ldg(ebuf + e + 2);
        int i3 = __ldg(ebuf + e + 3);
        float4 v0 = *reinterpret_cast<const float4*>(Wh + (size_t)i0 * DIM + q);
        float4 v1 = *reinterpret_cast<const float4*>(Wh + (size_t)i1 * DIM + q);
        float4 v2 = *reinterpret_cast<const float4*>(Wh + (size_t)i2 * DIM + q);
        float4 v3 = *reinterpret_cast<const float4*>(Wh + (size_t)i3 * DIM + q);
        s.x += (v0.x + v1.x) + (v2.x + v3.x);
        s.y += (v0.y + v1.y) + (v2.y + v3.y);
        s.z += (v0.z + v1.z) + (v2.z + v3.z);
        s.w += (v0.w + v1.w) + (v2.w + v3.w);
    }
    for (; e < e1; ++e) {
        int si = __ldg(ebuf + e);
        float4 v = *reinterpret_cast<const float4*>(Wh + (size_t)si * DIM + q);
        s.x += v.x; s.y += v.y; s.z += v.z; s.w += v.w;
    }
    float w = (e1 > e0) ? 1.0f / (float)(e1 - e0) : 0.f;
    s.x *= w; s.y *= w; s.z *= w; s.w *= w;

    if (mode == AGG_WRITE) {
        *reinterpret_cast<float4*>(agg + (size_t)node * DIM + q) = s;
    } else if (mode == AGG_ACC) {
        if (e0 == e1) return;
        float4* out = reinterpret_cast<float4*>(agg + (size_t)node * DIM + q);
        float4 a = *out;
        a.x += s.x; a.y += s.y; a.z += s.z; a.w += s.w;
        *out = a;
    } else {  // AGG_FINAL
        float4 a = *reinterpret_cast<const float4*>(agg + (size_t)node * DIM + q);
        a.x += s.x; a.y += s.y; a.z += s.z; a.w += s.w;
        a.x = a.x > 0.f ? a.x : 0.01f * a.x;
        a.y = a.y > 0.f ? a.y : 0.01f * a.y;
        a.z = a.z > 0.f ? a.z : 0.01f * a.z;
        a.w = a.w > 0.f ? a.w : 0.01f * a.w;
        __nv_bfloat162 h01, h23, l01, l23;
        h01.x = __float2bfloat16_rn(a.x);
        h01.y = __float2bfloat16_rn(a.y);
        h23.x = __float2bfloat16_rn(a.z);
        h23.y = __float2bfloat16_rn(a.w);
        l01.x = __float2bfloat16_rn(a.x - __bfloat162float(h01.x));
        l01.y = __float2bfloat16_rn(a.y - __bfloat162float(h01.y));
        l23.x = __float2bfloat16_rn(a.z - __bfloat162float(h23.x));
        l23.y = __float2bfloat16_rn(a.w - __bfloat162float(h23.y));
        uint2 hv, lv;
        hv.x = *reinterpret_cast<uint32_t*>(&h01);
        hv.y = *reinterpret_cast<uint32_t*>(&h23);
        lv.x = *reinterpret_cast<uint32_t*>(&l01);
        lv.y = *reinterpret_cast<uint32_t*>(&l23);
        *reinterpret_cast<uint2*>(hi + (size_t)node * DIM + q) = hv;
        *reinterpret_cast<uint2*>(lo + (size_t)node * DIM + q) = lv;
    }
}

// --------------------------------------------------------------------- host
extern "C" void kernel_launch(void* const* d_in, const int* in_sizes, int n_in,
                              void* d_out, int out_size)
{
    (void)n_in; (void)out_size;

    const float* emb[2] = {(const float*)d_in[0], (const float*)d_in[1]};
    const float *W1[4], *b1[4], *W2[4], *b2[4];
    const int *src[4], *dst[4];

    bool dict_order = (in_sizes[6] == NE);
    if (dict_order) {
        for (int t = 0; t < 4; t++) {
            const int base = 2 + 6 * t;
            W1[t]  = (const float*)d_in[base + 0];
            b1[t]  = (const float*)d_in[base + 1];
            W2[t]  = (const float*)d_in[base + 2];
            b2[t]  = (const float*)d_in[base + 3];
            src[t] = (const int*)  d_in[base + 4];
            dst[t] = (const int*)  d_in[base + 5];
        }
    } else {
        for (int t = 0; t < 4; t++) {
            W1[t]  = (const float*)d_in[2  + 2 * t];
            b1[t]  = (const float*)d_in[3  + 2 * t];
            W2[t]  = (const float*)d_in[10 + 2 * t];
            b2[t]  = (const float*)d_in[11 + 2 * t];
            src[t] = (const int*)  d_in[18 + 2 * t];
            dst[t] = (const int*)  d_in[19 + 2 * t];
        }
    }

    float *wh0, *wh1, *agg_ch, *agg_ge;
    int *cnt, *off, *cur, *bsum, *ebuf;
    __nv_bfloat16 *wt, *abf;
    cudaGetSymbolAddress((void**)&wh0,    g_Wh0);
    cudaGetSymbolAddress((void**)&wh1,    g_Wh1);
    cudaGetSymbolAddress((void**)&agg_ch, g_agg_ch);
    cudaGetSymbolAddress((void**)&agg_ge, g_agg_ge);
    cudaGetSymbolAddress((void**)&cnt,    g_cnt);
    cudaGetSymbolAddress((void**)&off,    g_off);
    cudaGetSymbolAddress((void**)&cur,    g_cur);
    cudaGetSymbolAddress((void**)&bsum,   g_bsum);
    cudaGetSymbolAddress((void**)&ebuf,   g_ebuf);
    cudaGetSymbolAddress((void**)&wt,     g_Wt);
    cudaGetSymbolAddress((void**)&abf,    g_Abf);

    cudaFuncSetAttribute(gemm_mma, cudaFuncAttributeMaxDynamicSharedMemorySize,
                         SMEM_BYTES);

    // lazily-created second stream + fork/join events (host-side handles only;
    // created on the first, uncaptured correctness call and reused — captured
    // event record/wait become pure graph DAG edges)
    static cudaStream_t s2 = nullptr;
    static cudaEvent_t evG[6], evA[6], evJoin;
    if (!s2) {
        cudaStreamCreateWithFlags(&s2, cudaStreamNonBlocking);
        for (int i = 0; i < 6; i++) {
            cudaEventCreateWithFlags(&evG[i], cudaEventDisableTiming);
            cudaEventCreateWithFlags(&evA[i], cudaEventDisableTiming);
        }
        cudaEventCreateWithFlags(&evJoin, cudaEventDisableTiming);
    }

    const size_t NB = (size_t)NNODE * DIM;
    __nv_bfloat16* Ah[4];
    __nv_bfloat16* Al[4];
    for (int b = 0; b < 4; b++) {
        Ah[b] = abf + (size_t)(2 * b + 0) * NB;
        Al[b] = abf + (size_t)(2 * b + 1) * NB;
    }

    const int n4 = NNODE * DIM / 4;
    dim3 ggrid(2, (NNODE + 127) / 128);

    // ---- prework on default stream: CSR build + splits ----
    zero_2i<<<(SCAN_N + 255) / 256, 256>>>(cnt, cur, SCAN_N);
    count_deg4<<<(4 * NE + 255) / 256, 256>>>(dst[0], dst[1], dst[2], dst[3], cnt);
    scan_p1<<<SCAN_BLKS, 256>>>(cnt, off, bsum);
    scan_p2<<<1, 256>>>(bsum);
    scan_p3<<<(SCAN_N + 255) / 256, 256>>>(off, bsum);
    scatter4<<<(4 * NE + 255) / 256, 256>>>(src[0], dst[0], src[1], dst[1],
                                            src[2], dst[2], src[3], dst[3],
                                            off, cur, ebuf);
    const float* wsrc[6] = {W1[0], W1[1], W1[2], W1[3], W2[1], W2[2]};
    for (int m = 0; m < 6; m++)
        split_w<<<256, 256>>>(wsrc[m], wt + (size_t)m * 131072,
                              wt + (size_t)m * 131072 + 65536);
    split_act<<<(n4 + 255) / 256, 256>>>(emb[0], Ah[0], Al[0], n4);
    split_act<<<(n4 + 255) / 256, 256>>>(emb[1], Ah[1], Al[1], n4);

    auto OFF = [&](int t) { return off + t * NNODE; };
    auto WT  = [&](int m) { return wt + (size_t)m * 131072; };

    // ===== two-stream pipeline: s1 (default) = GEMMs, s2 = aggregations =====
    // etypes: 0=ch2ge 1=ge2ch 2=ch2ch 3=ge2ge ; wh ping-pong 0/1/0/1/0/1
    // s1: G0 -> wh0
    gemm_mma<<<ggrid, 256, SMEM_BYTES>>>(Ah[0], Al[0], WT(0), WT(0) + 65536,
                                         b1[0], wh0, NNODE);
    cudaEventRecord(evG[0], 0);
    // s1: G1 -> wh1
    gemm_mma<<<ggrid, 256, SMEM_BYTES>>>(Ah[1], Al[1], WT(1), WT(1) + 65536,
                                         b1[1], wh1, NNODE);
    cudaEventRecord(evG[1], 0);

    // s2: A0 (wh0 -e0-> agg_ge WRITE)        [joins capture via evG[0]]
    cudaStreamWaitEvent(s2, evG[0], 0);
    csr_agg<<<AGG_BLOCKS, 256, 0, s2>>>(OFF(0), ebuf, wh0, agg_ge,
                                        nullptr, nullptr, AGG_WRITE);
    cudaEventRecord(evA[0], s2);
    // s2: A1 (wh1 -e1-> agg_ch WRITE)
    cudaStreamWaitEvent(s2, evG[1], 0);
    csr_agg<<<AGG_BLOCKS, 256, 0, s2>>>(OFF(1), ebuf, wh1, agg_ch,
                                        nullptr, nullptr, AGG_WRITE);
    cudaEventRecord(evA[1], s2);

    // s1: G3 -> wh0 (WAR on A0)
    cudaStreamWaitEvent(0, evA[0], 0);
    gemm_mma<<<ggrid, 256, SMEM_BYTES>>>(Ah[1], Al[1], WT(3), WT(3) + 65536,
                                         b1[3], wh0, NNODE);
    cudaEventRecord(evG[3], 0);
    // s2: A3 (wh0 -e3-> agg_ge FINAL -> Ah[3]/Al[3])
    cudaStreamWaitEvent(s2, evG[3], 0);
    csr_agg<<<AGG_BLOCKS, 256, 0, s2>>>(OFF(3), ebuf, wh0, agg_ge,
                                        Ah[3], Al[3], AGG_FINAL);
    cudaEventRecord(evA[3], s2);

    // s1: G2 -> wh1 (WAR on A1)
    cudaStreamWaitEvent(0, evA[1], 0);
    gemm_mma<<<ggrid, 256, SMEM_BYTES>>>(Ah[0], Al[0], WT(2), WT(2) + 65536,
                                         b1[2], wh1, NNODE);
    cudaEventRecord(evG[2], 0);
    // s2: A2 (wh1 -e2-> agg_ch FINAL -> Ah[2]/Al[2])
    cudaStreamWaitEvent(s2, evG[2], 0);
    csr_agg<<<AGG_BLOCKS, 256, 0, s2>>>(OFF(2), ebuf, wh1, agg_ch,
                                        Ah[2], Al[2], AGG_FINAL);
    cudaEventRecord(evA[2], s2);

    // s1: G4 (hid_ge x W2_ge2ch -> wh0; needs Ah[3] and wh0 free: evA[3])
    cudaStreamWaitEvent(0, evA[3], 0);
    gemm_mma<<<ggrid, 256, SMEM_BYTES>>>(Ah[3], Al[3], WT(4), WT(4) + 65536,
                                         b2[1], wh0, NNODE);
    cudaEventRecord(evG[4], 0);
    // s2: A4 (wh0 -e1-> d_out WRITE)
    cudaStreamWaitEvent(s2, evG[4], 0);
    csr_agg<<<AGG_BLOCKS, 256, 0, s2>>>(OFF(1), ebuf, wh0, (float*)d_out,
                                        nullptr, nullptr, AGG_WRITE);

    // s1: G5 (hid_ch x W2_ch2ch -> wh1; needs Ah[2] and wh1 free: evA[2])
    cudaStreamWaitEvent(0, evA[2], 0);
    gemm_mma<<<ggrid, 256, SMEM_BYTES>>>(Ah[2], Al[2], WT(5), WT(5) + 65536,
                                         b2[2], wh1, NNODE);
    cudaEventRecord(evG[5], 0);
    // s2: A5 (wh1 -e2-> d_out ACC)  — runs after A4 in s2 order
    cudaStreamWaitEvent(s2, evG[5], 0);
    csr_agg<<<AGG_BLOCKS, 256, 0, s2>>>(OFF(2), ebuf, wh1, (float*)d_out,
                                        nullptr, nullptr, AGG_ACC);

    // join s2 back into the default stream
    cudaEventRecord(evJoin, s2);
    cudaStreamWaitEvent(0, evJoin, 0);
}

// round 15
// speedup vs baseline: 1.4199x; 1.0436x over previous
#include <cuda_runtime.h>
#include <cuda_bf16.h>
#include <cstdint>

// ---------------------------------------------------------------------------
// Hetero-RGCN, 2 layers, output = chemical nodes.
// GEMM: mma.sync bf16 (HMMA) 3-term split, cp.async double-buffer + ldmatrix.
// Aggregation: CSR, unroll-4, 128-thread blocks (small reg/smem footprint so
//   they co-schedule beside the register-saturated GEMM), WRITE/ACC/FINAL.
// R15: CSR build moved to stream s2 (off critical path — only A0 needs it);
//   agg blocks shrunk 256->128 threads to enable partial co-residency with
//   GEMMs (R14's overlap failed on register-file exhaustion, not the DAG).
// ---------------------------------------------------------------------------

#define NNODE 50000
#define DIM   256
#define NE    400000
#define SCAN_N (4 * NNODE)                   // 200000
#define SCAN_BLKS ((SCAN_N + 1023) / 1024)   // 196

#define AGG_THREADS 128
#define AGG_BLOCKS  (NNODE * 64 / AGG_THREADS)   // 25000

#define AGG_WRITE 0
#define AGG_ACC   1
#define AGG_FINAL 2

__device__ __align__(16) float g_Wh0[NNODE * DIM];
__device__ __align__(16) float g_Wh1[NNODE * DIM];
__device__ __align__(16) float g_agg_ch[NNODE * DIM];
__device__ __align__(16) float g_agg_ge[NNODE * DIM];
__device__ __align__(16) int   g_cnt[SCAN_N];
__device__ __align__(16) int   g_off[SCAN_N + 1];
__device__ __align__(16) int   g_cur[SCAN_N];
__device__ __align__(16) int   g_bsum[SCAN_BLKS + 1];
__device__ __align__(16) int   g_ebuf[4 * NE];
__device__ __align__(16) __nv_bfloat16 g_Wt[6 * 2 * 65536];
__device__ __align__(16) __nv_bfloat16 g_Abf[4 * 2 * NNODE * DIM];

// ============================ small utility kernels =========================
__global__ void zero_2i(int* __restrict__ a, int* __restrict__ b, int n) {
    int i = blockIdx.x * blockDim.x + threadIdx.x;
    if (i < n) { a[i] = 0; b[i] = 0; }
}

__global__ void count_deg4(const int* __restrict__ d0, const int* __restrict__ d1,
                           const int* __restrict__ d2, const int* __restrict__ d3,
                           int* __restrict__ cnt) {
    int i = blockIdx.x * blockDim.x + threadIdx.x;
    if (i >= 4 * NE) return;
    int t = i / NE, e = i - t * NE;
    const int* d = (t == 0) ? d0 : (t == 1) ? d1 : (t == 2) ? d2 : d3;
    atomicAdd(&cnt[t * NNODE + d[e]], 1);
}

// ---- fast 3-pass exclusive scan over cnt[SCAN_N] -> off[SCAN_N+1] ----
__global__ __launch_bounds__(256)
void scan_p1(const int* __restrict__ cnt, int* __restrict__ off,
             int* __restrict__ bsum) {
    __shared__ int swarp[8];
    const int tid = threadIdx.x;
    const int lane = tid & 31, wrp = tid >> 5;
    const int i0 = blockIdx.x * 1024 + tid * 4;

    int v0 = 0, v1 = 0, v2 = 0, v3 = 0;
    if (i0 + 3 < SCAN_N) {
        int4 v = *reinterpret_cast<const int4*>(cnt + i0);
        v0 = v.x; v1 = v.y; v2 = v.z; v3 = v.w;
    } else {
        if (i0 + 0 < SCAN_N) v0 = cnt[i0 + 0];
        if (i0 + 1 < SCAN_N) v1 = cnt[i0 + 1];
        if (i0 + 2 < SCAN_N) v2 = cnt[i0 + 2];
        if (i0 + 3 < SCAN_N) v3 = cnt[i0 + 3];
    }
    int e1 = v0, e2 = v0 + v1, e3 = v0 + v1 + v2;
    int tsum = e3 + v3;

    int incl = tsum;
#pragma unroll
    for (int d = 1; d < 32; d <<= 1) {
        int u = __shfl_up_sync(0xffffffffu, incl, d);
        if (lane >= d) incl += u;
    }
    if (lane == 31) swarp[wrp] = incl;
    __syncthreads();
    if (wrp == 0 && lane < 8) {
        int w = swarp[lane];
        int wi = w;
#pragma unroll
        for (int d = 1; d < 8; d <<= 1) {
            int u = __shfl_up_sync(0xffu, wi, d);
            if (lane >= d) wi += u;
        }
        swarp[lane] = wi - w;
    }
    __syncthreads();
    int base = swarp[wrp] + (incl - tsum);

    if (i0 + 0 < SCAN_N) off[i0 + 0] = base;
    if (i0 + 1 < SCAN_N) off[i0 + 1] = base + e1;
    if (i0 + 2 < SCAN_N) off[i0 + 2] = base + e2;
    if (i0 + 3 < SCAN_N) off[i0 + 3] = base + e3;
    if (tid == 255) bsum[blockIdx.x] = base + tsum;
}

__global__ __launch_bounds__(256)
void scan_p2(int* __restrict__ bsum) {
    __shared__ int swarp[8];
    const int tid = threadIdx.x;
    const int lane = tid & 31, wrp = tid >> 5;
    int v = (tid < SCAN_BLKS) ? bsum[tid] : 0;
    int incl = v;
#pragma unroll
    for (int d = 1; d < 32; d <<= 1) {
        int u = __shfl_up_sync(0xffffffffu, incl, d);
        if (lane >= d) incl += u;
    }
    if (lane == 31) swarp[wrp] = incl;
    __syncthreads();
    if (wrp == 0 && lane < 8) {
        int w = swarp[lane];
        int wi = w;
#pragma unroll
        for (int d = 1; d < 8; d <<= 1) {
            int u = __shfl_up_sync(0xffu, wi, d);
            if (lane >= d) wi += u;
        }
        swarp[lane] = wi - w;
    }
    __syncthreads();
    if (tid < SCAN_BLKS) bsum[tid] = swarp[wrp] + (incl - v);
}

__global__ void scan_p3(int* __restrict__ off, const int* __restrict__ bsum) {
    int i = blockIdx.x * blockDim.x + threadIdx.x;
    if (i < SCAN_N) off[i] += bsum[i >> 10];
    if (i == 0) off[SCAN_N] = 4 * NE;
}

__global__ void scatter4(const int* __restrict__ s0, const int* __restrict__ d0,
                         const int* __restrict__ s1, const int* __restrict__ d1,
                         const int* __restrict__ s2, const int* __restrict__ d2,
                         const int* __restrict__ s3, const int* __restrict__ d3,
                         const int* __restrict__ off, int* __restrict__ cur,
                         int* __restrict__ ebuf) {
    int i = blockIdx.x * blockDim.x + threadIdx.x;
    if (i >= 4 * NE) return;
    int t = i / NE, e = i - t * NE;
    const int* s = (t == 0) ? s0 : (t == 1) ? s1 : (t == 2) ? s2 : s3;
    const int* d = (t == 0) ? d0 : (t == 1) ? d1 : (t == 2) ? d2 : d3;
    int dd = t * NNODE + d[e];
    int p = atomicAdd(&cur[dd], 1);
    ebuf[off[dd] + p] = s[e];
}

// Transpose + bf16 hi/lo split of one 256x256 weight: out[n][k] = W[k][n]
__global__ void split_w(const float* __restrict__ W,
                        __nv_bfloat16* __restrict__ hi,
                        __nv_bfloat16* __restrict__ lo) {
    int i = blockIdx.x * 256 + threadIdx.x;
    int n = i >> 8, k = i & 255;
    float w = W[k * 256 + n];
    __nv_bfloat16 h = __float2bfloat16_rn(w);
    hi[i] = h;
    lo[i] = __float2bfloat16_rn(w - __bfloat162float(h));
}

// fp32 activations -> bf16 hi/lo (input embeddings)
__global__ void split_act(const float* __restrict__ x,
                          __nv_bfloat16* __restrict__ hi,
                          __nv_bfloat16* __restrict__ lo, int n4) {
    int i = blockIdx.x * blockDim.x + threadIdx.x;
    if (i >= n4) return;
    float4 v = reinterpret_cast<const float4*>(x)[i];
    __nv_bfloat162 h01, h23, l01, l23;
    h01.x = __float2bfloat16_rn(v.x);
    h01.y = __float2bfloat16_rn(v.y);
    h23.x = __float2bfloat16_rn(v.z);
    h23.y = __float2bfloat16_rn(v.w);
    l01.x = __float2bfloat16_rn(v.x - __bfloat162float(h01.x));
    l01.y = __float2bfloat16_rn(v.y - __bfloat162float(h01.y));
    l23.x = __float2bfloat16_rn(v.z - __bfloat162float(h23.x));
    l23.y = __float2bfloat16_rn(v.w - __bfloat162float(h23.y));
    uint2 hv, lv;
    hv.x = *reinterpret_cast<uint32_t*>(&h01);
    hv.y = *reinterpret_cast<uint32_t*>(&h23);
    lv.x = *reinterpret_cast<uint32_t*>(&l01);
    lv.y = *reinterpret_cast<uint32_t*>(&l23);
    *reinterpret_cast<uint2*>(hi + (size_t)i * 4) = hv;
    *reinterpret_cast<uint2*>(lo + (size_t)i * 4) = lv;
}

// ====================== mma.sync bf16 split GEMM ============================
#define AST 40
#define STG_A_HI 0
#define STG_A_LO 10240
#define STG_B_HI 20480
#define STG_B_LO 30720
#define STG_BYTES 40960
#define SMEM_BYTES (2 * STG_BYTES)   // 81920

__device__ __forceinline__ uint32_t smem_u32(const void* p) {
    uint32_t a;
    asm("{ .reg .u64 t; cvta.to.shared.u64 t, %1; cvt.u32.u64 %0, t; }"
        : "=r"(a) : "l"(p));
    return a;
}

__device__ __forceinline__ void cp16(uint32_t s, const void* g, int sz) {
    asm volatile("cp.async.cg.shared.global [%0], [%1], 16, %2;"
                 :: "r"(s), "l"(g), "r"(sz));
}

__device__ __forceinline__ void ldm_x4(uint32_t* r, uint32_t addr) {
    asm volatile("ldmatrix.sync.aligned.m8n8.x4.shared.b16 {%0,%1,%2,%3}, [%4];"
                 : "=r"(r[0]), "=r"(r[1]), "=r"(r[2]), "=r"(r[3]) : "r"(addr));
}

__device__ __forceinline__ void mma_bf16(float* c, const uint32_t* a,
                                         const uint32_t* b) {
    asm volatile(
        "mma.sync.aligned.m16n8k16.row.col.f32.bf16.bf16.f32 "
        "{%0,%1,%2,%3}, {%4,%5,%6,%7}, {%8,%9}, {%0,%1,%2,%3};"
        : "+f"(c[0]), "+f"(c[1]), "+f"(c[2]), "+f"(c[3])
        : "r"(a[0]), "r"(a[1]), "r"(a[2]), "r"(a[3]), "r"(b[0]), "r"(b[1]));
}

__global__ __launch_bounds__(256, 2)
void gemm_mma(const __nv_bfloat16* __restrict__ Ahi,
              const __nv_bfloat16* __restrict__ Alo,
              const __nv_bfloat16* __restrict__ Bhi,
              const __nv_bfloat16* __restrict__ Blo,
              const float* __restrict__ bias,
              float* __restrict__ C, int M)
{
    extern __shared__ char smc[];
    const uint32_t smb = smem_u32(smc);

    const int tid = threadIdx.x;
    const int wid = tid >> 5;
    const int lid = tid & 31;
    const int wr = wid & 1;
    const int wc = wid >> 1;
    const int g = lid >> 2;
    const int t = lid & 3;
    const int row0 = blockIdx.y * 128;
    const int col0 = blockIdx.x * 128;

    const int a_row_l = wr * 64 + (lid & 7) + ((lid >> 3) & 1) * 8;
    const int a_col_l = ((lid >> 4) & 1) * 8;
    const int b_row_l = wc * 32 + (lid & 7) + ((lid >> 4) & 1) * 8;
    const int b_col_l = ((lid >> 3) & 1) * 8;

    float acc[4][4][4];
#pragma unroll
    for (int i = 0; i < 4; i++)
#pragma unroll
        for (int j = 0; j < 4; j++)
#pragma unroll
            for (int k = 0; k < 4; k++) acc[i][j][k] = 0.f;

#define ISSUE_STAGE(stage, k0)                                                 \
    do {                                                                       \
        uint32_t sb = smb + (stage) * STG_BYTES;                               \
        _Pragma("unroll")                                                      \
        for (int it = 0; it < 2; ++it) {                                       \
            int i = it * 256 + tid;                                            \
            int r = i >> 2, ch = i & 3;                                        \
            uint32_t so = (uint32_t)(r * 80 + ch * 16);                        \
            int gr = row0 + r;                                                 \
            int sz = (gr < M) ? 16 : 0;                                        \
            size_t aoff = (size_t)(gr < M ? gr : 0) * 256 + (k0) + ch * 8;     \
            cp16(sb + STG_A_HI + so, Ahi + aoff, sz);                          \
            cp16(sb + STG_A_LO + so, Alo + aoff, sz);                          \
            size_t boff = (size_t)(col0 + r) * 256 + (k0) + ch * 8;            \
            cp16(sb + STG_B_HI + so, Bhi + boff, 16);                          \
            cp16(sb + STG_B_LO + so, Blo + boff, 16);                          \
        }                                                                      \
        asm volatile("cp.async.commit_group;" ::: "memory");                   \
    } while (0)

    ISSUE_STAGE(0, 0);

    for (int kb = 0; kb < 8; ++kb) {
        const int st = kb & 1;
        if (kb < 7) {
            ISSUE_STAGE(st ^ 1, (kb + 1) * 32);
            asm volatile("cp.async.wait_group 1;" ::: "memory");
        } else {
            asm volatile("cp.async.wait_group 0;" ::: "memory");
        }
        __syncthreads();

        const uint32_t stg = smb + st * STG_BYTES;

#pragma unroll
        for (int ks = 0; ks < 2; ++ks) {
            const int kk = ks * 16;
            uint32_t af[4][4], bh[2][4], bl[2][4];

#pragma unroll
            for (int np = 0; np < 2; ++np) {
                uint32_t boff = (uint32_t)((b_row_l + np * 16) * AST + kk + b_col_l) * 2;
                ldm_x4(bh[np], stg + STG_B_HI + boff);
                ldm_x4(bl[np], stg + STG_B_LO + boff);
            }
#pragma unroll
            for (int mt = 0; mt < 4; ++mt) {
                uint32_t aoff = (uint32_t)((a_row_l + mt * 16) * AST + kk + a_col_l) * 2;
                ldm_x4(af[mt], stg + STG_A_HI + aoff);
            }
#pragma unroll
            for (int mt = 0; mt < 4; ++mt)
#pragma unroll
                for (int nt = 0; nt < 4; ++nt)
                    mma_bf16(acc[mt][nt], af[mt], &bh[nt >> 1][(nt & 1) * 2]);
#pragma unroll
            for (int mt = 0; mt < 4; ++mt)
#pragma unroll
                for (int nt = 0; nt < 4; ++nt)
                    mma_bf16(acc[mt][nt], af[mt], &bl[nt >> 1][(nt & 1) * 2]);
#pragma unroll
            for (int mt = 0; mt < 4; ++mt) {
                uint32_t aoff = (uint32_t)((a_row_l + mt * 16) * AST + kk + a_col_l) * 2;
                ldm_x4(af[mt], stg + STG_A_LO + aoff);
            }
#pragma unroll
            for (int mt = 0; mt < 4; ++mt)
#pragma unroll
                for (int nt = 0; nt < 4; ++nt)
                    mma_bf16(acc[mt][nt], af[mt], &bh[nt >> 1][(nt & 1) * 2]);
        }
        __syncthreads();
    }

#pragma unroll
    for (int nt = 0; nt < 4; ++nt) {
        const int gc = col0 + wc * 32 + nt * 8 + t * 2;
        float2 bb = *reinterpret_cast<const float2*>(bias + gc);
#pragma unroll
        for (int mt = 0; mt < 4; ++mt) {
            int r0 = row0 + wr * 64 + mt * 16 + g;
            if (r0 < M) {
                float2 o;
                o.x = acc[mt][nt][0] + bb.x;
                o.y = acc[mt][nt][1] + bb.y;
                *reinterpret_cast<float2*>(C + (size_t)r0 * 256 + gc) = o;
            }
            if (r0 + 8 < M) {
                float2 o;
                o.x = acc[mt][nt][2] + bb.x;
                o.y = acc[mt][nt][3] + bb.y;
                *reinterpret_cast<float2*>(C + (size_t)(r0 + 8) * 256 + gc) = o;
            }
        }
    }
}

// ============== CSR mean aggregation (unroll-4, 3 modes) ===================
// 128-thread blocks (2 nodes/block, 64 thr/node): ~5K regs + 0 smem per block
// so agg blocks can slot in beside the register-saturated GEMM.
__global__ __launch_bounds__(AGG_THREADS)
void csr_agg(const int* __restrict__ off, const int* __restrict__ ebuf,
             const float* __restrict__ Wh, float* __restrict__ agg,
             __nv_bfloat16* __restrict__ hi,
             __nv_bfloat16* __restrict__ lo, int mode)
{
    int idx = blockIdx.x * AGG_THREADS + threadIdx.x;
    int node = idx >> 6;
    if (node >= NNODE) return;
    int q = (idx & 63) << 2;
    int e0 = __ldg(off + node), e1 = __ldg(off + node + 1);

    float4 s = make_float4(0.f, 0.f, 0.f, 0.f);
    int e = e0;
    for (; e + 4 <= e1; e += 4) {
        int i0 = __ldg(ebuf + e + 0);
        int i1 = __ldg(ebuf + e + 1);
        int i2 = __ldg(ebuf + e + 2);
        int i3 = __ldg(ebuf + e + 3);
        float4 v0 = *reinterpret_cast<const float4*>(Wh + (size_t)i0 * DIM + q);
        float4 v1 = *reinterpret_cast<const float4*>(Wh + (size_t)i1 * DIM + q);
        float4 v2 = *reinterpret_cast<const float4*>(Wh + (size_t)i2 * DIM + q);
        float4 v3 = *reinterpret_cast<const float4*>(Wh + (size_t)i3 * DIM + q);
        s.x += (v0.x + v1.x) + (v2.x + v3.x);
        s.y += (v0.y + v1.y) + (v2.y + v3.y);
        s.z += (v0.z + v1.z) + (v2.z + v3.z);
        s.w += (v0.w + v1.w) + (v2.w + v3.w);
    }
    for (; e < e1; ++e) {
        int si = __ldg(ebuf + e);
        float4 v = *reinterpret_cast<const float4*>(Wh + (size_t)si * DIM + q);
        s.x += v.x; s.y += v.y; s.z += v.z; s.w += v.w;
    }
    float w = (e1 > e0) ? 1.0f / (float)(e1 - e0) : 0.f;
    s.x *= w; s.y *= w; s.z *= w; s.w *= w;

    if (mode == AGG_WRITE) {
        *reinterpret_cast<float4*>(agg + (size_t)node * DIM + q) = s;
    } else if (mode == AGG_ACC) {
        if (e0 == e1) return;
        float4* out = reinterpret_cast<float4*>(agg + (size_t)node * DIM + q);
        float4 a = *out;
        a.x += s.x; a.y += s.y; a.z += s.z; a.w += s.w;
        *out = a;
    } else {  // AGG_FINAL
        float4 a = *reinterpret_cast<const float4*>(agg + (size_t)node * DIM + q);
        a.x += s.x; a.y += s.y; a.z += s.z; a.w += s.w;
        a.x = a.x > 0.f ? a.x : 0.01f * a.x;
        a.y = a.y > 0.f ? a.y : 0.01f * a.y;
        a.z = a.z > 0.f ? a.z : 0.01f * a.z;
        a.w = a.w > 0.f ? a.w : 0.01f * a.w;
        __nv_bfloat162 h01, h23, l01, l23;
        h01.x = __float2bfloat16_rn(a.x);
        h01.y = __float2bfloat16_rn(a.y);
        h23.x = __float2bfloat16_rn(a.z);
        h23.y = __float2bfloat16_rn(a.w);
        l01.x = __float2bfloat16_rn(a.x - __bfloat162float(h01.x));
        l01.y = __float2bfloat16_rn(a.y - __bfloat162float(h01.y));
        l23.x = __float2bfloat16_rn(a.z - __bfloat162float(h23.x));
        l23.y = __float2bfloat16_rn(a.w - __bfloat162float(h23.y));
        uint2 hv, lv;
        hv.x = *reinterpret_cast<uint32_t*>(&h01);
        hv.y = *reinterpret_cast<uint32_t*>(&h23);
        lv.x = *reinterpret_cast<uint32_t*>(&l01);
        lv.y = *reinterpret_cast<uint32_t*>(&l23);
        *reinterpret_cast<uint2*>(hi + (size_t)node * DIM + q) = hv;
        *reinterpret_cast<uint2*>(lo + (size_t)node * DIM + q) = lv;
    }
}

// --------------------------------------------------------------------- host
extern "C" void kernel_launch(void* const* d_in, const int* in_sizes, int n_in,
                              void* d_out, int out_size)
{
    (void)n_in; (void)out_size;

    const float* emb[2] = {(const float*)d_in[0], (const float*)d_in[1]};
    const float *W1[4], *b1[4], *W2[4], *b2[4];
    const int *src[4], *dst[4];

    bool dict_order = (in_sizes[6] == NE);
    if (dict_order) {
        for (int t = 0; t < 4; t++) {
            const int base = 2 + 6 * t;
            W1[t]  = (const float*)d_in[base + 0];
            b1[t]  = (const float*)d_in[base + 1];
            W2[t]  = (const float*)d_in[base + 2];
            b2[t]  = (const float*)d_in[base + 3];
            src[t] = (const int*)  d_in[base + 4];
            dst[t] = (const int*)  d_in[base + 5];
        }
    } else {
        for (int t = 0; t < 4; t++) {
            W1[t]  = (const float*)d_in[2  + 2 * t];
            b1[t]  = (const float*)d_in[3  + 2 * t];
            W2[t]  = (const float*)d_in[10 + 2 * t];
            b2[t]  = (const float*)d_in[11 + 2 * t];
            src[t] = (const int*)  d_in[18 + 2 * t];
            dst[t] = (const int*)  d_in[19 + 2 * t];
        }
    }

    float *wh0, *wh1, *agg_ch, *agg_ge;
    int *cnt, *off, *cur, *bsum, *ebuf;
    __nv_bfloat16 *wt, *abf;
    cudaGetSymbolAddress((void**)&wh0,    g_Wh0);
    cudaGetSymbolAddress((void**)&wh1,    g_Wh1);
    cudaGetSymbolAddress((void**)&agg_ch, g_agg_ch);
    cudaGetSymbolAddress((void**)&agg_ge, g_agg_ge);
    cudaGetSymbolAddress((void**)&cnt,    g_cnt);
    cudaGetSymbolAddress((void**)&off,    g_off);
    cudaGetSymbolAddress((void**)&cur,    g_cur);
    cudaGetSymbolAddress((void**)&bsum,   g_bsum);
    cudaGetSymbolAddress((void**)&ebuf,   g_ebuf);
    cudaGetSymbolAddress((void**)&wt,     g_Wt);
    cudaGetSymbolAddress((void**)&abf,    g_Abf);

    cudaFuncSetAttribute(gemm_mma, cudaFuncAttributeMaxDynamicSharedMemorySize,
                         SMEM_BYTES);

    static cudaStream_t s2 = nullptr;
    static cudaEvent_t evFork, evG[6], evA[6], evJoin;
    if (!s2) {
        cudaStreamCreateWithFlags(&s2, cudaStreamNonBlocking);
        cudaEventCreateWithFlags(&evFork, cudaEventDisableTiming);
        for (int i = 0; i < 6; i++) {
            cudaEventCreateWithFlags(&evG[i], cudaEventDisableTiming);
            cudaEventCreateWithFlags(&evA[i], cudaEventDisableTiming);
        }
        cudaEventCreateWithFlags(&evJoin, cudaEventDisableTiming);
    }

    const size_t NB = (size_t)NNODE * DIM;
    __nv_bfloat16* Ah[4];
    __nv_bfloat16* Al[4];
    for (int b = 0; b < 4; b++) {
        Ah[b] = abf + (size_t)(2 * b + 0) * NB;
        Al[b] = abf + (size_t)(2 * b + 1) * NB;
    }

    const int n4 = NNODE * DIM / 4;
    dim3 ggrid(2, (NNODE + 127) / 128);

    auto OFF = [&](int t) { return off + t * NNODE; };
    auto WT  = [&](int m) { return wt + (size_t)m * 131072; };

    // ---- fork: s2 builds CSR (only A0 needs it) while s1 does splits+GEMMs
    cudaEventRecord(evFork, 0);
    cudaStreamWaitEvent(s2, evFork, 0);

    // s2: CSR build chain
    zero_2i<<<(SCAN_N + 255) / 256, 256, 0, s2>>>(cnt, cur, SCAN_N);
    count_deg4<<<(4 * NE + 255) / 256, 256, 0, s2>>>(dst[0], dst[1], dst[2],
                                                     dst[3], cnt);
    scan_p1<<<SCAN_BLKS, 256, 0, s2>>>(cnt, off, bsum);
    scan_p2<<<1, 256, 0, s2>>>(bsum);
    scan_p3<<<(SCAN_N + 255) / 256, 256, 0, s2>>>(off, bsum);
    scatter4<<<(4 * NE + 255) / 256, 256, 0, s2>>>(src[0], dst[0], src[1], dst[1],
                                                   src[2], dst[2], src[3], dst[3],
                                                   off, cur, ebuf);

    // s1: weight + embedding splits
    const float* wsrc[6] = {W1[0], W1[1], W1[2], W1[3], W2[1], W2[2]};
    for (int m = 0; m < 6; m++)
        split_w<<<256, 256>>>(wsrc[m], wt + (size_t)m * 131072,
                              wt + (size_t)m * 131072 + 65536);
    split_act<<<(n4 + 255) / 256, 256>>>(emb[0], Ah[0], Al[0], n4);
    split_act<<<(n4 + 255) / 256, 256>>>(emb[1], Ah[1], Al[1], n4);

    // ===== two-stream pipeline: s1 = GEMMs, s2 = aggregations =====
    // etypes: 0=ch2ge 1=ge2ch 2=ch2ch 3=ge2ge ; wh ping-pong
    gemm_mma<<<ggrid, 256, SMEM_BYTES>>>(Ah[0], Al[0], WT(0), WT(0) + 65536,
                                         b1[0], wh0, NNODE);
    cudaEventRecord(evG[0], 0);
    gemm_mma<<<ggrid, 256, SMEM_BYTES>>>(Ah[1], Al[1], WT(1), WT(1) + 65536,
                                         b1[1], wh1, NNODE);
    cudaEventRecord(evG[1], 0);

    // s2: A0 (wh0 -e0-> agg_ge WRITE) — CSR ready by s2 ordering
    cudaStreamWaitEvent(s2, evG[0], 0);
    csr_agg<<<AGG_BLOCKS, AGG_THREADS, 0, s2>>>(OFF(0), ebuf, wh0, agg_ge,
                                                nullptr, nullptr, AGG_WRITE);
    cudaEventRecord(evA[0], s2);
    // s2: A1 (wh1 -e1-> agg_ch WRITE)
    cudaStreamWaitEvent(s2, evG[1], 0);
    csr_agg<<<AGG_BLOCKS, AGG_THREADS, 0, s2>>>(OFF(1), ebuf, wh1, agg_ch,
                                                nullptr, nullptr, AGG_WRITE);
    cudaEventRecord(evA[1], s2);

    // s1: G3 -> wh0 (WAR on A0)
    cudaStreamWaitEvent(0, evA[0], 0);
    gemm_mma<<<ggrid, 256, SMEM_BYTES>>>(Ah[1], Al[1], WT(3), WT(3) + 65536,
                                         b1[3], wh0, NNODE);
    cudaEventRecord(evG[3], 0);
    // s2: A3 (wh0 -e3-> agg_ge FINAL -> Ah[3]/Al[3])
    cudaStreamWaitEvent(s2, evG[3], 0);
    csr_agg<<<AGG_BLOCKS, AGG_THREADS, 0, s2>>>(OFF(3), ebuf, wh0, agg_ge,
                                                Ah[3], Al[3], AGG_FINAL);
    cudaEventRecord(evA[3], s2);

    // s1: G2 -> wh1 (WAR on A1)
    cudaStreamWaitEvent(0, evA[1], 0);
    gemm_mma<<<ggrid, 256, SMEM_BYTES>>>(Ah[0], Al[0], WT(2), WT(2) + 65536,
                                         b1[2], wh1, NNODE);
    cudaEventRecord(evG[2], 0);
    // s2: A2 (wh1 -e2-> agg_ch FINAL -> Ah[2]/Al[2])
    cudaStreamWaitEvent(s2, evG[2], 0);
    csr_agg<<<AGG_BLOCKS, AGG_THREADS, 0, s2>>>(OFF(2), ebuf, wh1, agg_ch,
                                                Ah[2], Al[2], AGG_FINAL);
    cudaEventRecord(evA[2], s2);

    // s1: G4 (hid_ge x W2_ge2ch -> wh0; needs Ah[3]/wh0 free: evA[3])
    cudaStreamWaitEvent(0, evA[3], 0);
    gemm_mma<<<ggrid, 256, SMEM_BYTES>>>(Ah[3], Al[3], WT(4), WT(4) + 65536,
                                         b2[1], wh0, NNODE);
    cudaEventRecord(evG[4], 0);
    // s2: A4 (wh0 -e1-> d_out WRITE)
    cudaStreamWaitEvent(s2, evG[4], 0);
    csr_agg<<<AGG_BLOCKS, AGG_THREADS, 0, s2>>>(OFF(1), ebuf, wh0, (float*)d_out,
                                                nullptr, nullptr, AGG_WRITE);

    // s1: G5 (hid_ch x W2_ch2ch -> wh1; needs Ah[2]/wh1 free: evA[2])
    cudaStreamWaitEvent(0, evA[2], 0);
    gemm_mma<<<ggrid, 256, SMEM_BYTES>>>(Ah[2], Al[2], WT(5), WT(5) + 65536,
                                         b2[2], wh1, NNODE);
    cudaEventRecord(evG[5], 0);
    // s2: A5 (wh1 -e2-> d_out ACC) — after A4 in s2 order
    cudaStreamWaitEvent(s2, evG[5], 0);
    csr_agg<<<AGG_BLOCKS, AGG_THREADS, 0, s2>>>(OFF(2), ebuf, wh1, (float*)d_out,
                                                nullptr, nullptr, AGG_ACC);

    // join
    cudaEventRecord(evJoin, s2);
    cudaStreamWaitEvent(0, evJoin, 0);
}

// round 16
// speedup vs baseline: 1.4759x; 1.0395x over previous
#include <cuda_runtime.h>
#include <cuda_bf16.h>
#include <cstdint>

// ---------------------------------------------------------------------------
// Hetero-RGCN, 2 layers, output = chemical nodes.
// GEMM: mma.sync bf16 (HMMA) 3-term split, cp.async double-buffer + ldmatrix.
// Aggregation: CSR, unroll-4, 128-thread blocks, WRITE/ACC/FINAL modes.
// R16: 4 dedicated Wh buffers (one per layer-1 etype) delete ALL WAR waits —
//   s1 runs 4 GEMMs back-to-back while s2 drains aggs; G3 hoisted to 2nd so
//   A3 (FINAL -> Ah[3], feeds G4) gets the longest overlap window.
// ---------------------------------------------------------------------------

#define NNODE 50000
#define DIM   256
#define NE    400000
#define SCAN_N (4 * NNODE)                   // 200000
#define SCAN_BLKS ((SCAN_N + 1023) / 1024)   // 196

#define AGG_THREADS 128
#define AGG_BLOCKS  (NNODE * 64 / AGG_THREADS)   // 25000

#define AGG_WRITE 0
#define AGG_ACC   1
#define AGG_FINAL 2

__device__ __align__(16) float g_Wh0[NNODE * DIM];
__device__ __align__(16) float g_Wh1[NNODE * DIM];
__device__ __align__(16) float g_Wh2[NNODE * DIM];
__device__ __align__(16) float g_Wh3[NNODE * DIM];
__device__ __align__(16) float g_agg_ch[NNODE * DIM];
__device__ __align__(16) float g_agg_ge[NNODE * DIM];
__device__ __align__(16) int   g_cnt[SCAN_N];
__device__ __align__(16) int   g_off[SCAN_N + 1];
__device__ __align__(16) int   g_cur[SCAN_N];
__device__ __align__(16) int   g_bsum[SCAN_BLKS + 1];
__device__ __align__(16) int   g_ebuf[4 * NE];
__device__ __align__(16) __nv_bfloat16 g_Wt[6 * 2 * 65536];
__device__ __align__(16) __nv_bfloat16 g_Abf[4 * 2 * NNODE * DIM];

// ============================ small utility kernels =========================
__global__ void zero_2i(int* __restrict__ a, int* __restrict__ b, int n) {
    int i = blockIdx.x * blockDim.x + threadIdx.x;
    if (i < n) { a[i] = 0; b[i] = 0; }
}

__global__ void count_deg4(const int* __restrict__ d0, const int* __restrict__ d1,
                           const int* __restrict__ d2, const int* __restrict__ d3,
                           int* __restrict__ cnt) {
    int i = blockIdx.x * blockDim.x + threadIdx.x;
    if (i >= 4 * NE) return;
    int t = i / NE, e = i - t * NE;
    const int* d = (t == 0) ? d0 : (t == 1) ? d1 : (t == 2) ? d2 : d3;
    atomicAdd(&cnt[t * NNODE + d[e]], 1);
}

// ---- fast 3-pass exclusive scan over cnt[SCAN_N] -> off[SCAN_N+1] ----
__global__ __launch_bounds__(256)
void scan_p1(const int* __restrict__ cnt, int* __restrict__ off,
             int* __restrict__ bsum) {
    __shared__ int swarp[8];
    const int tid = threadIdx.x;
    const int lane = tid & 31, wrp = tid >> 5;
    const int i0 = blockIdx.x * 1024 + tid * 4;

    int v0 = 0, v1 = 0, v2 = 0, v3 = 0;
    if (i0 + 3 < SCAN_N) {
        int4 v = *reinterpret_cast<const int4*>(cnt + i0);
        v0 = v.x; v1 = v.y; v2 = v.z; v3 = v.w;
    } else {
        if (i0 + 0 < SCAN_N) v0 = cnt[i0 + 0];
        if (i0 + 1 < SCAN_N) v1 = cnt[i0 + 1];
        if (i0 + 2 < SCAN_N) v2 = cnt[i0 + 2];
        if (i0 + 3 < SCAN_N) v3 = cnt[i0 + 3];
    }
    int e1 = v0, e2 = v0 + v1, e3 = v0 + v1 + v2;
    int tsum = e3 + v3;

    int incl = tsum;
#pragma unroll
    for (int d = 1; d < 32; d <<= 1) {
        int u = __shfl_up_sync(0xffffffffu, incl, d);
        if (lane >= d) incl += u;
    }
    if (lane == 31) swarp[wrp] = incl;
    __syncthreads();
    if (wrp == 0 && lane < 8) {
        int w = swarp[lane];
        int wi = w;
#pragma unroll
        for (int d = 1; d < 8; d <<= 1) {
            int u = __shfl_up_sync(0xffu, wi, d);
            if (lane >= d) wi += u;
        }
        swarp[lane] = wi - w;
    }
    __syncthreads();
    int base = swarp[wrp] + (incl - tsum);

    if (i0 + 0 < SCAN_N) off[i0 + 0] = base;
    if (i0 + 1 < SCAN_N) off[i0 + 1] = base + e1;
    if (i0 + 2 < SCAN_N) off[i0 + 2] = base + e2;
    if (i0 + 3 < SCAN_N) off[i0 + 3] = base + e3;
    if (tid == 255) bsum[blockIdx.x] = base + tsum;
}

__global__ __launch_bounds__(256)
void scan_p2(int* __restrict__ bsum) {
    __shared__ int swarp[8];
    const int tid = threadIdx.x;
    const int lane = tid & 31, wrp = tid >> 5;
    int v = (tid < SCAN_BLKS) ? bsum[tid] : 0;
    int incl = v;
#pragma unroll
    for (int d = 1; d < 32; d <<= 1) {
        int u = __shfl_up_sync(0xffffffffu, incl, d);
        if (lane >= d) incl += u;
    }
    if (lane == 31) swarp[wrp] = incl;
    __syncthreads();
    if (wrp == 0 && lane < 8) {
        int w = swarp[lane];
        int wi = w;
#pragma unroll
        for (int d = 1; d < 8; d <<= 1) {
            int u = __shfl_up_sync(0xffu, wi, d);
            if (lane >= d) wi += u;
        }
        swarp[lane] = wi - w;
    }
    __syncthreads();
    if (tid < SCAN_BLKS) bsum[tid] = swarp[wrp] + (incl - v);
}

__global__ void scan_p3(int* __restrict__ off, const int* __restrict__ bsum) {
    int i = blockIdx.x * blockDim.x + threadIdx.x;
    if (i < SCAN_N) off[i] += bsum[i >> 10];
    if (i == 0) off[SCAN_N] = 4 * NE;
}

__global__ void scatter4(const int* __restrict__ s0, const int* __restrict__ d0,
                         const int* __restrict__ s1, const int* __restrict__ d1,
                         const int* __restrict__ s2, const int* __restrict__ d2,
                         const int* __restrict__ s3, const int* __restrict__ d3,
                         const int* __restrict__ off, int* __restrict__ cur,
                         int* __restrict__ ebuf) {
    int i = blockIdx.x * blockDim.x + threadIdx.x;
    if (i >= 4 * NE) return;
    int t = i / NE, e = i - t * NE;
    const int* s = (t == 0) ? s0 : (t == 1) ? s1 : (t == 2) ? s2 : s3;
    const int* d = (t == 0) ? d0 : (t == 1) ? d1 : (t == 2) ? d2 : d3;
    int dd = t * NNODE + d[e];
    int p = atomicAdd(&cur[dd], 1);
    ebuf[off[dd] + p] = s[e];
}

// Transpose + bf16 hi/lo split of one 256x256 weight: out[n][k] = W[k][n]
__global__ void split_w(const float* __restrict__ W,
                        __nv_bfloat16* __restrict__ hi,
                        __nv_bfloat16* __restrict__ lo) {
    int i = blockIdx.x * 256 + threadIdx.x;
    int n = i >> 8, k = i & 255;
    float w = W[k * 256 + n];
    __nv_bfloat16 h = __float2bfloat16_rn(w);
    hi[i] = h;
    lo[i] = __float2bfloat16_rn(w - __bfloat162float(h));
}

// fp32 activations -> bf16 hi/lo (input embeddings)
__global__ void split_act(const float* __restrict__ x,
                          __nv_bfloat16* __restrict__ hi,
                          __nv_bfloat16* __restrict__ lo, int n4) {
    int i = blockIdx.x * blockDim.x + threadIdx.x;
    if (i >= n4) return;
    float4 v = reinterpret_cast<const float4*>(x)[i];
    __nv_bfloat162 h01, h23, l01, l23;
    h01.x = __float2bfloat16_rn(v.x);
    h01.y = __float2bfloat16_rn(v.y);
    h23.x = __float2bfloat16_rn(v.z);
    h23.y = __float2bfloat16_rn(v.w);
    l01.x = __float2bfloat16_rn(v.x - __bfloat162float(h01.x));
    l01.y = __float2bfloat16_rn(v.y - __bfloat162float(h01.y));
    l23.x = __float2bfloat16_rn(v.z - __bfloat162float(h23.x));
    l23.y = __float2bfloat16_rn(v.w - __bfloat162float(h23.y));
    uint2 hv, lv;
    hv.x = *reinterpret_cast<uint32_t*>(&h01);
    hv.y = *reinterpret_cast<uint32_t*>(&h23);
    lv.x = *reinterpret_cast<uint32_t*>(&l01);
    lv.y = *reinterpret_cast<uint32_t*>(&l23);
    *reinterpret_cast<uint2*>(hi + (size_t)i * 4) = hv;
    *reinterpret_cast<uint2*>(lo + (size_t)i * 4) = lv;
}

// ====================== mma.sync bf16 split GEMM ============================
#define AST 40
#define STG_A_HI 0
#define STG_A_LO 10240
#define STG_B_HI 20480
#define STG_B_LO 30720
#define STG_BYTES 40960
#define SMEM_BYTES (2 * STG_BYTES)   // 81920

__device__ __forceinline__ uint32_t smem_u32(const void* p) {
    uint32_t a;
    asm("{ .reg .u64 t; cvta.to.shared.u64 t, %1; cvt.u32.u64 %0, t; }"
        : "=r"(a) : "l"(p));
    return a;
}

__device__ __forceinline__ void cp16(uint32_t s, const void* g, int sz) {
    asm volatile("cp.async.cg.shared.global [%0], [%1], 16, %2;"
                 :: "r"(s), "l"(g), "r"(sz));
}

__device__ __forceinline__ void ldm_x4(uint32_t* r, uint32_t addr) {
    asm volatile("ldmatrix.sync.aligned.m8n8.x4.shared.b16 {%0,%1,%2,%3}, [%4];"
                 : "=r"(r[0]), "=r"(r[1]), "=r"(r[2]), "=r"(r[3]) : "r"(addr));
}

__device__ __forceinline__ void mma_bf16(float* c, const uint32_t* a,
                                         const uint32_t* b) {
    asm volatile(
        "mma.sync.aligned.m16n8k16.row.col.f32.bf16.bf16.f32 "
        "{%0,%1,%2,%3}, {%4,%5,%6,%7}, {%8,%9}, {%0,%1,%2,%3};"
        : "+f"(c[0]), "+f"(c[1]), "+f"(c[2]), "+f"(c[3])
        : "r"(a[0]), "r"(a[1]), "r"(a[2]), "r"(a[3]), "r"(b[0]), "r"(b[1]));
}

__global__ __launch_bounds__(256, 2)
void gemm_mma(const __nv_bfloat16* __restrict__ Ahi,
              const __nv_bfloat16* __restrict__ Alo,
              const __nv_bfloat16* __restrict__ Bhi,
              const __nv_bfloat16* __restrict__ Blo,
              const float* __restrict__ bias,
              float* __restrict__ C, int M)
{
    extern __shared__ char smc[];
    const uint32_t smb = smem_u32(smc);

    const int tid = threadIdx.x;
    const int wid = tid >> 5;
    const int lid = tid & 31;
    const int wr = wid & 1;
    const int wc = wid >> 1;
    const int g = lid >> 2;
    const int t = lid & 3;
    const int row0 = blockIdx.y * 128;
    const int col0 = blockIdx.x * 128;

    const int a_row_l = wr * 64 + (lid & 7) + ((lid >> 3) & 1) * 8;
    const int a_col_l = ((lid >> 4) & 1) * 8;
    const int b_row_l = wc * 32 + (lid & 7) + ((lid >> 4) & 1) * 8;
    const int b_col_l = ((lid >> 3) & 1) * 8;

    float acc[4][4][4];
#pragma unroll
    for (int i = 0; i < 4; i++)
#pragma unroll
        for (int j = 0; j < 4; j++)
#pragma unroll
            for (int k = 0; k < 4; k++) acc[i][j][k] = 0.f;

#define ISSUE_STAGE(stage, k0)                                                 \
    do {                                                                       \
        uint32_t sb = smb + (stage) * STG_BYTES;                               \
        _Pragma("unroll")                                                      \
        for (int it = 0; it < 2; ++it) {                                       \
            int i = it * 256 + tid;                                            \
            int r = i >> 2, ch = i & 3;                                        \
            uint32_t so = (uint32_t)(r * 80 + ch * 16);                        \
            int gr = row0 + r;                                                 \
            int sz = (gr < M) ? 16 : 0;                                        \
            size_t aoff = (size_t)(gr < M ? gr : 0) * 256 + (k0) + ch * 8;     \
            cp16(sb + STG_A_HI + so, Ahi + aoff, sz);                          \
            cp16(sb + STG_A_LO + so, Alo + aoff, sz);                          \
            size_t boff = (size_t)(col0 + r) * 256 + (k0) + ch * 8;            \
            cp16(sb + STG_B_HI + so, Bhi + boff, 16);                          \
            cp16(sb + STG_B_LO + so, Blo + boff, 16);                          \
        }                                                                      \
        asm volatile("cp.async.commit_group;" ::: "memory");                   \
    } while (0)

    ISSUE_STAGE(0, 0);

    for (int kb = 0; kb < 8; ++kb) {
        const int st = kb & 1;
        if (kb < 7) {
            ISSUE_STAGE(st ^ 1, (kb + 1) * 32);
            asm volatile("cp.async.wait_group 1;" ::: "memory");
        } else {
            asm volatile("cp.async.wait_group 0;" ::: "memory");
        }
        __syncthreads();

        const uint32_t stg = smb + st * STG_BYTES;

#pragma unroll
        for (int ks = 0; ks < 2; ++ks) {
            const int kk = ks * 16;
            uint32_t af[4][4], bh[2][4], bl[2][4];

#pragma unroll
            for (int np = 0; np < 2; ++np) {
                uint32_t boff = (uint32_t)((b_row_l + np * 16) * AST + kk + b_col_l) * 2;
                ldm_x4(bh[np], stg + STG_B_HI + boff);
                ldm_x4(bl[np], stg + STG_B_LO + boff);
            }
#pragma unroll
            for (int mt = 0; mt < 4; ++mt) {
                uint32_t aoff = (uint32_t)((a_row_l + mt * 16) * AST + kk + a_col_l) * 2;
                ldm_x4(af[mt], stg + STG_A_HI + aoff);
            }
#pragma unroll
            for (int mt = 0; mt < 4; ++mt)
#pragma unroll
                for (int nt = 0; nt < 4; ++nt)
                    mma_bf16(acc[mt][nt], af[mt], &bh[nt >> 1][(nt & 1) * 2]);
#pragma unroll
            for (int mt = 0; mt < 4; ++mt)
#pragma unroll
                for (int nt = 0; nt < 4; ++nt)
                    mma_bf16(acc[mt][nt], af[mt], &bl[nt >> 1][(nt & 1) * 2]);
#pragma unroll
            for (int mt = 0; mt < 4; ++mt) {
                uint32_t aoff = (uint32_t)((a_row_l + mt * 16) * AST + kk + a_col_l) * 2;
                ldm_x4(af[mt], stg + STG_A_LO + aoff);
            }
#pragma unroll
            for (int mt = 0; mt < 4; ++mt)
#pragma unroll
                for (int nt = 0; nt < 4; ++nt)
                    mma_bf16(acc[mt][nt], af[mt], &bh[nt >> 1][(nt & 1) * 2]);
        }
        __syncthreads();
    }

#pragma unroll
    for (int nt = 0; nt < 4; ++nt) {
        const int gc = col0 + wc * 32 + nt * 8 + t * 2;
        float2 bb = *reinterpret_cast<const float2*>(bias + gc);
#pragma unroll
        for (int mt = 0; mt < 4; ++mt) {
            int r0 = row0 + wr * 64 + mt * 16 + g;
            if (r0 < M) {
                float2 o;
                o.x = acc[mt][nt][0] + bb.x;
                o.y = acc[mt][nt][1] + bb.y;
                *reinterpret_cast<float2*>(C + (size_t)r0 * 256 + gc) = o;
            }
            if (r0 + 8 < M) {
                float2 o;
                o.x = acc[mt][nt][2] + bb.x;
                o.y = acc[mt][nt][3] + bb.y;
                *reinterpret_cast<float2*>(C + (size_t)(r0 + 8) * 256 + gc) = o;
            }
        }
    }
}

// ============== CSR mean aggregation (unroll-4, 3 modes) ===================
__global__ __launch_bounds__(AGG_THREADS)
void csr_agg(const int* __restrict__ off, const int* __restrict__ ebuf,
             const float* __restrict__ Wh, float* __restrict__ agg,
             __nv_bfloat16* __restrict__ hi,
             __nv_bfloat16* __restrict__ lo, int mode)
{
    int idx = blockIdx.x * AGG_THREADS + threadIdx.x;
    int node = idx >> 6;
    if (node >= NNODE) return;
    int q = (idx & 63) << 2;
    int e0 = __ldg(off + node), e1 = __ldg(off + node + 1);

    float4 s = make_float4(0.f, 0.f, 0.f, 0.f);
    int e = e0;
    for (; e + 4 <= e1; e += 4) {
        int i0 = __ldg(ebuf + e + 0);
        int i1 = __ldg(ebuf + e + 1);
        int i2 = __ldg(ebuf + e + 2);
        int i3 = __ldg(ebuf + e + 3);
        float4 v0 = *reinterpret_cast<const float4*>(Wh + (size_t)i0 * DIM + q);
        float4 v1 = *reinterpret_cast<const float4*>(Wh + (size_t)i1 * DIM + q);
        float4 v2 = *reinterpret_cast<const float4*>(Wh + (size_t)i2 * DIM + q);
        float4 v3 = *reinterpret_cast<const float4*>(Wh + (size_t)i3 * DIM + q);
        s.x += (v0.x + v1.x) + (v2.x + v3.x);
        s.y += (v0.y + v1.y) + (v2.y + v3.y);
        s.z += (v0.z + v1.z) + (v2.z + v3.z);
        s.w += (v0.w + v1.w) + (v2.w + v3.w);
    }
    for (; e < e1; ++e) {
        int si = __ldg(ebuf + e);
        float4 v = *reinterpret_cast<const float4*>(Wh + (size_t)si * DIM + q);
        s.x += v.x; s.y += v.y; s.z += v.z; s.w += v.w;
    }
    float w = (e1 > e0) ? 1.0f / (float)(e1 - e0) : 0.f;
    s.x *= w; s.y *= w; s.z *= w; s.w *= w;

    if (mode == AGG_WRITE) {
        *reinterpret_cast<float4*>(agg + (size_t)node * DIM + q) = s;
    } else if (mode == AGG_ACC) {
        if (e0 == e1) return;
        float4* out = reinterpret_cast<float4*>(agg + (size_t)node * DIM + q);
        float4 a = *out;
        a.x += s.x; a.y += s.y; a.z += s.z; a.w += s.w;
        *out = a;
    } else {  // AGG_FINAL
        float4 a = *reinterpret_cast<const float4*>(agg + (size_t)node * DIM + q);
        a.x += s.x; a.y += s.y; a.z += s.z; a.w += s.w;
        a.x = a.x > 0.f ? a.x : 0.01f * a.x;
        a.y = a.y > 0.f ? a.y : 0.01f * a.y;
        a.z = a.z > 0.f ? a.z : 0.01f * a.z;
        a.w = a.w > 0.f ? a.w : 0.01f * a.w;
        __nv_bfloat162 h01, h23, l01, l23;
        h01.x = __float2bfloat16_rn(a.x);
        h01.y = __float2bfloat16_rn(a.y);
        h23.x = __float2bfloat16_rn(a.z);
        h23.y = __float2bfloat16_rn(a.w);
        l01.x = __float2bfloat16_rn(a.x - __bfloat162float(h01.x));
        l01.y = __float2bfloat16_rn(a.y - __bfloat162float(h01.y));
        l23.x = __float2bfloat16_rn(a.z - __bfloat162float(h23.x));
        l23.y = __float2bfloat16_rn(a.w - __bfloat162float(h23.y));
        uint2 hv, lv;
        hv.x = *reinterpret_cast<uint32_t*>(&h01);
        hv.y = *reinterpret_cast<uint32_t*>(&h23);
        lv.x = *reinterpret_cast<uint32_t*>(&l01);
        lv.y = *reinterpret_cast<uint32_t*>(&l23);
        *reinterpret_cast<uint2*>(hi + (size_t)node * DIM + q) = hv;
        *reinterpret_cast<uint2*>(lo + (size_t)node * DIM + q) = lv;
    }
}

// --------------------------------------------------------------------- host
extern "C" void kernel_launch(void* const* d_in, const int* in_sizes, int n_in,
                              void* d_out, int out_size)
{
    (void)n_in; (void)out_size;

    const float* emb[2] = {(const float*)d_in[0], (const float*)d_in[1]};
    const float *W1[4], *b1[4], *W2[4], *b2[4];
    const int *src[4], *dst[4];

    bool dict_order = (in_sizes[6] == NE);
    if (dict_order) {
        for (int t = 0; t < 4; t++) {
            const int base = 2 + 6 * t;
            W1[t]  = (const float*)d_in[base + 0];
            b1[t]  = (const float*)d_in[base + 1];
            W2[t]  = (const float*)d_in[base + 2];
            b2[t]  = (const float*)d_in[base + 3];
            src[t] = (const int*)  d_in[base + 4];
            dst[t] = (const int*)  d_in[base + 5];
        }
    } else {
        for (int t = 0; t < 4; t++) {
            W1[t]  = (const float*)d_in[2  + 2 * t];
            b1[t]  = (const float*)d_in[3  + 2 * t];
            W2[t]  = (const float*)d_in[10 + 2 * t];
            b2[t]  = (const float*)d_in[11 + 2 * t];
            src[t] = (const int*)  d_in[18 + 2 * t];
            dst[t] = (const int*)  d_in[19 + 2 * t];
        }
    }

    float *wh[4], *agg_ch, *agg_ge;
    int *cnt, *off, *cur, *bsum, *ebuf;
    __nv_bfloat16 *wt, *abf;
    cudaGetSymbolAddress((void**)&wh[0],  g_Wh0);
    cudaGetSymbolAddress((void**)&wh[1],  g_Wh1);
    cudaGetSymbolAddress((void**)&wh[2],  g_Wh2);
    cudaGetSymbolAddress((void**)&wh[3],  g_Wh3);
    cudaGetSymbolAddress((void**)&agg_ch, g_agg_ch);
    cudaGetSymbolAddress((void**)&agg_ge, g_agg_ge);
    cudaGetSymbolAddress((void**)&cnt,    g_cnt);
    cudaGetSymbolAddress((void**)&off,    g_off);
    cudaGetSymbolAddress((void**)&cur,    g_cur);
    cudaGetSymbolAddress((void**)&bsum,   g_bsum);
    cudaGetSymbolAddress((void**)&ebuf,   g_ebuf);
    cudaGetSymbolAddress((void**)&wt,     g_Wt);
    cudaGetSymbolAddress((void**)&abf,    g_Abf);

    cudaFuncSetAttribute(gemm_mma, cudaFuncAttributeMaxDynamicSharedMemorySize,
                         SMEM_BYTES);

    static cudaStream_t s2 = nullptr;
    static cudaEvent_t evFork, evG[6], evA[6], evJoin;
    if (!s2) {
        cudaStreamCreateWithFlags(&s2, cudaStreamNonBlocking);
        cudaEventCreateWithFlags(&evFork, cudaEventDisableTiming);
        for (int i = 0; i < 6; i++) {
            cudaEventCreateWithFlags(&evG[i], cudaEventDisableTiming);
            cudaEventCreateWithFlags(&evA[i], cudaEventDisableTiming);
        }
        cudaEventCreateWithFlags(&evJoin, cudaEventDisableTiming);
    }

    const size_t NB = (size_t)NNODE * DIM;
    __nv_bfloat16* Ah[4];
    __nv_bfloat16* Al[4];
    for (int b = 0; b < 4; b++) {
        Ah[b] = abf + (size_t)(2 * b + 0) * NB;
        Al[b] = abf + (size_t)(2 * b + 1) * NB;
    }

    const int n4 = NNODE * DIM / 4;
    dim3 ggrid(2, (NNODE + 127) / 128);

    auto OFF = [&](int t) { return off + t * NNODE; };
    auto WT  = [&](int m) { return wt + (size_t)m * 131072; };

    // ---- fork: s2 builds CSR while s1 does splits + layer-1 GEMMs ----
    cudaEventRecord(evFork, 0);
    cudaStreamWaitEvent(s2, evFork, 0);

    zero_2i<<<(SCAN_N + 255) / 256, 256, 0, s2>>>(cnt, cur, SCAN_N);
    count_deg4<<<(4 * NE + 255) / 256, 256, 0, s2>>>(dst[0], dst[1], dst[2],
                                                     dst[3], cnt);
    scan_p1<<<SCAN_BLKS, 256, 0, s2>>>(cnt, off, bsum);
    scan_p2<<<1, 256, 0, s2>>>(bsum);
    scan_p3<<<(SCAN_N + 255) / 256, 256, 0, s2>>>(off, bsum);
    scatter4<<<(4 * NE + 255) / 256, 256, 0, s2>>>(src[0], dst[0], src[1], dst[1],
                                                   src[2], dst[2], src[3], dst[3],
                                                   off, cur, ebuf);

    const float* wsrc[6] = {W1[0], W1[1], W1[2], W1[3], W2[1], W2[2]};
    for (int m = 0; m < 6; m++)
        split_w<<<256, 256>>>(wsrc[m], wt + (size_t)m * 131072,
                              wt + (size_t)m * 131072 + 65536);
    split_act<<<(n4 + 255) / 256, 256>>>(emb[0], Ah[0], Al[0], n4);
    split_act<<<(n4 + 255) / 256, 256>>>(emb[1], Ah[1], Al[1], n4);

    // ===== layer 1: 4 GEMMs back-to-back (no WAR — dedicated Wh each) =====
    // s1 order: G0, G3 (hoisted: A3 FINAL feeds G4), G1, G2
    // etypes: 0=ch2ge(src ch) 1=ge2ch(src ge) 2=ch2ch(src ch) 3=ge2ge(src ge)
    gemm_mma<<<ggrid, 256, SMEM_BYTES>>>(Ah[0], Al[0], WT(0), WT(0) + 65536,
                                         b1[0], wh[0], NNODE);
    cudaEventRecord(evG[0], 0);
    gemm_mma<<<ggrid, 256, SMEM_BYTES>>>(Ah[1], Al[1], WT(3), WT(3) + 65536,
                                         b1[3], wh[3], NNODE);
    cudaEventRecord(evG[3], 0);
    gemm_mma<<<ggrid, 256, SMEM_BYTES>>>(Ah[1], Al[1], WT(1), WT(1) + 65536,
                                         b1[1], wh[1], NNODE);
    cudaEventRecord(evG[1], 0);
    gemm_mma<<<ggrid, 256, SMEM_BYTES>>>(Ah[0], Al[0], WT(2), WT(2) + 65536,
                                         b1[2], wh[2], NNODE);
    cudaEventRecord(evG[2], 0);

    // s2 aggs (in-order): A0 (ge WRITE), A3 (ge FINAL->Ah[3]),
    //                     A1 (ch WRITE), A2 (ch FINAL->Ah[2])
    cudaStreamWaitEvent(s2, evG[0], 0);
    csr_agg<<<AGG_BLOCKS, AGG_THREADS, 0, s2>>>(OFF(0), ebuf, wh[0], agg_ge,
                                                nullptr, nullptr, AGG_WRITE);
    cudaEventRecord(evA[0], s2);
    cudaStreamWaitEvent(s2, evG[3], 0);
    csr_agg<<<AGG_BLOCKS, AGG_THREADS, 0, s2>>>(OFF(3), ebuf, wh[3], agg_ge,
                                                Ah[3], Al[3], AGG_FINAL);
    cudaEventRecord(evA[3], s2);
    cudaStreamWaitEvent(s2, evG[1], 0);
    csr_agg<<<AGG_BLOCKS, AGG_THREADS, 0, s2>>>(OFF(1), ebuf, wh[1], agg_ch,
                                                nullptr, nullptr, AGG_WRITE);
    cudaEventRecord(evA[1], s2);
    cudaStreamWaitEvent(s2, evG[2], 0);
    csr_agg<<<AGG_BLOCKS, AGG_THREADS, 0, s2>>>(OFF(2), ebuf, wh[2], agg_ch,
                                                Ah[2], Al[2], AGG_FINAL);
    cudaEventRecord(evA[2], s2);

    // ===== layer 2 =====
    // G4: hid_ge x W2_ge2ch -> wh[0]  (needs Ah[3]=evA[3]; WAR wh[0]=evA[0])
    cudaStreamWaitEvent(0, evA[3], 0);
    cudaStreamWaitEvent(0, evA[0], 0);
    gemm_mma<<<ggrid, 256, SMEM_BYTES>>>(Ah[3], Al[3], WT(4), WT(4) + 65536,
                                         b2[1], wh[0], NNODE);
    cudaEventRecord(evG[4], 0);
    // s2: A4 (wh[0] -e1-> d_out WRITE)
    cudaStreamWaitEvent(s2, evG[4], 0);
    csr_agg<<<AGG_BLOCKS, AGG_THREADS, 0, s2>>>(OFF(1), ebuf, wh[0], (float*)d_out,
                                                nullptr, nullptr, AGG_WRITE);

    // G5: hid_ch x W2_ch2ch -> wh[1]  (needs Ah[2]=evA[2]; WAR wh[1]=evA[1])
    cudaStreamWaitEvent(0, evA[2], 0);
    cudaStreamWaitEvent(0, evA[1], 0);
    gemm_mma<<<ggrid, 256, SMEM_BYTES>>>(Ah[2], Al[2], WT(5), WT(5) + 65536,
                                         b2[2], wh[1], NNODE);
    cudaEventRecord(evG[5], 0);
    // s2: A5 (wh[1] -e2-> d_out ACC) — after A4 in s2 order
    cudaStreamWaitEvent(s2, evG[5], 0);
    csr_agg<<<AGG_BLOCKS, AGG_THREADS, 0, s2>>>(OFF(2), ebuf, wh[1], (float*)d_out,
                                                nullptr, nullptr, AGG_ACC);

    cudaEventRecord(evJoin, s2);
    cudaStreamWaitEvent(0, evJoin, 0);
}